// round 4
// baseline (speedup 1.0000x reference)
#include <cuda_runtime.h>
#include <cuda_bf16.h>
#include <math.h>

typedef unsigned long long ull;

// ---------------- packed f32x2 helpers ----------------
__device__ __forceinline__ ull pack2(float lo, float hi) {
    ull r; asm("mov.b64 %0, {%1, %2};" : "=l"(r) : "f"(lo), "f"(hi)); return r;
}
__device__ __forceinline__ ull bc2(float v) { return pack2(v, v); }
__device__ __forceinline__ void ffma2(ull& d, ull a, ull b) {
    asm("fma.rn.f32x2 %0, %1, %2, %0;" : "+l"(d) : "l"(a), "l"(b));
}
__device__ __forceinline__ float lo32(ull v) { return __uint_as_float((unsigned)v); }
__device__ __forceinline__ float hi32(ull v) { return __uint_as_float((unsigned)(v >> 32)); }

// ---------------- scratch ----------------
#define BATCH 32
__device__ float g_A[BATCH*64*64*64];
__device__ float g_B[BATCH*128*32*32];
__device__ float g_C[BATCH*128*32*32];
__device__ float g_R[BATCH*32*32*32];
__device__ float g_Z[BATCH*64*32*32];
__device__ float g_Q[BATCH*64*32*32];
__device__ int   g_hist[512];
__device__ float g_ssep[256];

__global__ void zero_kernel(int* hist) {
    int t = blockIdx.x * blockDim.x + threadIdx.x;
    if (t < 512) hist[t] = 0;
}

// ---------------- conv1: k=4 s=2 p=1, Cin=3 (scalar, small) ----------------
__global__ void conv_k4s2_kernel(const float* __restrict__ in, const float* __restrict__ w,
                                 const float* __restrict__ bias, float* __restrict__ out,
                                 int Cin, int Hin, int Win, int Cout, int Hout, int Wout,
                                 int outRelu)
{
    __shared__ float s_in[8][34][36];
    __shared__ float s_w[8][8][16];
    int tid = threadIdx.x;
    int ntx = Wout >> 4;
    int tx0 = (blockIdx.x % ntx) << 4, ty0 = (blockIdx.x / ntx) << 4;
    int ocb = blockIdx.y << 3;
    int b = blockIdx.z;
    int px = tid & 15, py = tid >> 4;
    float acc[8];
#pragma unroll
    for (int i = 0; i < 8; i++) acc[i] = 0.f;

    for (int c0 = 0; c0 < Cin; c0 += 8) {
        int cc = min(8, Cin - c0);
        for (int i = tid; i < cc * 34 * 34; i += 256) {
            int ci = i / (34*34); int rr = (i / 34) % 34; int col = i % 34;
            int gy = 2*ty0 - 1 + rr, gx = 2*tx0 - 1 + col;
            float v = 0.f;
            if ((unsigned)gy < (unsigned)Hin && (unsigned)gx < (unsigned)Win)
                v = in[((b*Cin + c0 + ci)*Hin + gy)*Win + gx];
            s_in[ci][rr][col] = v;
        }
        for (int i = tid; i < 8 * cc * 16; i += 256) {
            int oc = i / (cc*16); int ci = (i / 16) % cc; int k = i & 15;
            s_w[oc][ci][k] = w[((ocb+oc)*Cin + c0 + ci)*16 + k];
        }
        __syncthreads();
        for (int ci = 0; ci < cc; ci++) {
            float v[16];
#pragma unroll
            for (int ky = 0; ky < 4; ky++)
#pragma unroll
                for (int kx = 0; kx < 4; kx++)
                    v[ky*4+kx] = s_in[ci][2*py + ky][2*px + kx];
#pragma unroll
            for (int oc = 0; oc < 8; oc++) {
                float a = acc[oc];
#pragma unroll
                for (int k = 0; k < 16; k++) a += v[k] * s_w[oc][ci][k];
                acc[oc] = a;
            }
        }
        __syncthreads();
    }
#pragma unroll
    for (int oc = 0; oc < 8; oc++) {
        float r = acc[oc] + bias[ocb + oc];
        if (outRelu) r = fmaxf(r, 0.f);
        out[((b*Cout + ocb + oc)*Hout + ty0 + py)*Wout + tx0 + px] = r;
    }
}

// ---------------- conv2: k=4 s=2 p=1 packed f32x2 (in 64x64 -> out 32x32) ----------------
// 256 thr = 32 pos x 8 ocg (4 oc each -> 32 oc/block). grid(4, Cout/32, B)
__global__ void __launch_bounds__(256, 3)
convk4s2_f2_kernel(const float* __restrict__ in, const float* __restrict__ w,
                   const float* __restrict__ bias, float* __restrict__ out,
                   int Cin, int Cout)
{
    __shared__ float s_in[4][18][68];
    __shared__ ull s_w[4][16][16];
    int tid = threadIdx.x;
    int pos = tid & 31, ocg = tid >> 5;
    int posx = pos & 7, posy = pos >> 3;
    int col0 = posx * 4, row0 = posy * 2;
    int ry0 = blockIdx.x * 8;
    int ocb = blockIdx.y * 32;
    int b = blockIdx.z;
    ull acc[2][4][2];
#pragma unroll
    for (int r = 0; r < 2; r++)
#pragma unroll
        for (int c = 0; c < 4; c++)
#pragma unroll
            for (int j = 0; j < 2; j++) acc[r][c][j] = 0ull;

    float* swf = (float*)s_w;
    for (int c0 = 0; c0 < Cin; c0 += 4) {
        for (int i = tid; i < 4*18*66; i += 256) {
            int ci = i / (18*66); int rr = (i / 66) % 18; int cc = i % 66;
            int gy = 2*ry0 - 1 + rr, gx = cc - 1;
            float v = 0.f;
            if ((unsigned)gy < 64u && (unsigned)gx < 64u)
                v = in[((b*Cin + c0 + ci)*64 + gy)*64 + gx];
            s_in[ci][rr][cc] = v;
        }
        for (int i = tid; i < 32*64; i += 256) {
            int ocl = i >> 6; int t = i & 63; int ci = t >> 4; int k = t & 15;
            swf[(ci*16 + k)*32 + ocl] = w[(ocb + ocl)*Cin*16 + (c0 + ci)*16 + k];
        }
        __syncthreads();
#pragma unroll
        for (int ci = 0; ci < 4; ci++) {
#pragma unroll
            for (int ky = 0; ky < 4; ky++) {
#pragma unroll
                for (int r = 0; r < 2; r++) {
                    int rr = 2*row0 + 2*r + ky;
                    ull vb[10];
#pragma unroll
                    for (int t = 0; t < 10; t++) vb[t] = bc2(s_in[ci][rr][2*col0 + t]);
#pragma unroll
                    for (int kx = 0; kx < 4; kx++) {
                        ull wr[2];
#pragma unroll
                        for (int j = 0; j < 2; j++) wr[j] = s_w[ci][ky*4+kx][ocg*2 + j];
#pragma unroll
                        for (int c = 0; c < 4; c++)
#pragma unroll
                            for (int j = 0; j < 2; j++)
                                ffma2(acc[r][c][j], vb[2*c+kx], wr[j]);
                    }
                }
            }
        }
        __syncthreads();
    }
#pragma unroll
    for (int r = 0; r < 2; r++)
#pragma unroll
        for (int c = 0; c < 4; c++)
#pragma unroll
            for (int j = 0; j < 2; j++) {
                int oc = ocb + ocg*4 + 2*j;
                int row = ry0 + row0 + r, col = col0 + c;
                float v0 = fmaxf(lo32(acc[r][c][j]) + bias[oc], 0.f);
                float v1 = fmaxf(hi32(acc[r][c][j]) + bias[oc+1], 0.f);
                out[((b*Cout + oc)*32 + row)*32 + col] = v0;
                out[((b*Cout + oc+1)*32 + row)*32 + col] = v1;
            }
}

// ---------------- conv 3x3 s=1 p=1 packed f32x2, H=W=32, 32 oc/block ----------------
// POS = RH*4 threads cover RH rows x 32 cols (2r x 4c each); ocg = 256/POS groups of TOC oc.
// Requires (256/POS)*TOC == 32.
template<int RH, int TOC>
__global__ void __launch_bounds__(256, 3)
conv3x3_f2_kernel(const float* __restrict__ in, const float* __restrict__ w,
                  const float* __restrict__ bias, float* __restrict__ out,
                  int Cin, int Cout, int inRelu)
{
    constexpr int POS = RH * 4;
    constexpr int NCP = TOC / 2;
    __shared__ float s_in[8][RH+2][34];
    __shared__ ull s_w[8][9][16];
    int tid = threadIdx.x;
    int pos = tid % POS, ocg = tid / POS;
    int posx = pos & 7, posy = pos >> 3;
    int col0 = posx * 4, row0 = posy * 2;
    int ry0 = blockIdx.x * RH;
    int ocb = blockIdx.y * 32;
    int b = blockIdx.z;
    ull acc[2][4][NCP];
#pragma unroll
    for (int r = 0; r < 2; r++)
#pragma unroll
        for (int c = 0; c < 4; c++)
#pragma unroll
            for (int j = 0; j < NCP; j++) acc[r][c][j] = 0ull;

    float* swf = (float*)s_w;
    for (int c0 = 0; c0 < Cin; c0 += 8) {
        for (int i = tid; i < 8*(RH+2)*34; i += 256) {
            int ci = i / ((RH+2)*34); int rr = (i / 34) % (RH+2); int cc = i % 34;
            int gy = ry0 - 1 + rr, gx = cc - 1;
            float v = 0.f;
            if ((unsigned)gy < 32u && (unsigned)gx < 32u)
                v = in[((b*Cin + c0 + ci)*32 + gy)*32 + gx];
            if (inRelu) v = fmaxf(v, 0.f);
            s_in[ci][rr][cc] = v;
        }
        for (int i = tid; i < 32*72; i += 256) {
            int ocl = i / 72; int t = i % 72; int ci = t / 9; int k = t % 9;
            swf[(ci*9 + k)*32 + ocl] = w[(ocb + ocl)*Cin*9 + (c0 + ci)*9 + k];
        }
        __syncthreads();
#pragma unroll
        for (int ci = 0; ci < 8; ci++) {
#pragma unroll
            for (int ky = 0; ky < 3; ky++) {
                ull vb0[6], vb1[6];
#pragma unroll
                for (int c = 0; c < 6; c++) {
                    vb0[c] = bc2(s_in[ci][row0 + ky][col0 + c]);
                    vb1[c] = bc2(s_in[ci][row0 + ky + 1][col0 + c]);
                }
#pragma unroll
                for (int kx = 0; kx < 3; kx++) {
                    ull wr[NCP];
#pragma unroll
                    for (int j = 0; j < NCP; j++) wr[j] = s_w[ci][ky*3+kx][ocg*NCP + j];
#pragma unroll
                    for (int c = 0; c < 4; c++)
#pragma unroll
                        for (int j = 0; j < NCP; j++) {
                            ffma2(acc[0][c][j], vb0[c+kx], wr[j]);
                            ffma2(acc[1][c][j], vb1[c+kx], wr[j]);
                        }
                }
            }
        }
        __syncthreads();
    }
#pragma unroll
    for (int r = 0; r < 2; r++)
#pragma unroll
        for (int c = 0; c < 4; c++)
#pragma unroll
            for (int j = 0; j < NCP; j++) {
                int oc = ocb + ocg*TOC + 2*j;
                int row = ry0 + row0 + r, col = col0 + c;
                float b0 = bias ? bias[oc] : 0.f;
                float b1 = bias ? bias[oc+1] : 0.f;
                out[((b*Cout + oc)*32 + row)*32 + col] = lo32(acc[r][c][j]) + b0;
                out[((b*Cout + oc+1)*32 + row)*32 + col] = hi32(acc[r][c][j]) + b1;
            }
}

// ---------------- conv 1x1 packed: relu(in) @ w, +bias, +res ----------------
__global__ void __launch_bounds__(256, 3)
conv1x1_f2_kernel(const float* __restrict__ in, const float* __restrict__ w,
                  const float* __restrict__ bias, const float* __restrict__ hres,
                  float* __restrict__ out, int Cin, int Cout)
{
    __shared__ ull s_w[128][16];
    int tid = threadIdx.x;
    int pos = tid & 63, ocg = tid >> 6;
    int s0 = blockIdx.x * 256 + pos * 4;
    int ocb = blockIdx.y * 32;
    int b = blockIdx.z;
    float* swf = (float*)s_w;
    for (int i = tid; i < Cin * 32; i += 256) {
        int ocl = i / Cin; int ci = i % Cin;
        swf[ci*32 + ocl] = w[(ocb + ocl)*Cin + ci];
    }
    __syncthreads();
    ull acc[4][4];
#pragma unroll
    for (int p = 0; p < 4; p++)
#pragma unroll
        for (int j = 0; j < 4; j++) acc[p][j] = 0ull;

    for (int ci = 0; ci < Cin; ci++) {
        float4 iv = *(const float4*)&in[((size_t)(b*Cin + ci) << 10) + s0];
        ull b0 = bc2(fmaxf(iv.x, 0.f)), b1 = bc2(fmaxf(iv.y, 0.f));
        ull b2 = bc2(fmaxf(iv.z, 0.f)), b3 = bc2(fmaxf(iv.w, 0.f));
        ull wr[4];
#pragma unroll
        for (int j = 0; j < 4; j++) wr[j] = s_w[ci][ocg*4 + j];
#pragma unroll
        for (int j = 0; j < 4; j++) {
            ffma2(acc[0][j], b0, wr[j]);
            ffma2(acc[1][j], b1, wr[j]);
            ffma2(acc[2][j], b2, wr[j]);
            ffma2(acc[3][j], b3, wr[j]);
        }
    }
#pragma unroll
    for (int j = 0; j < 4; j++) {
#pragma unroll
        for (int lane = 0; lane < 2; lane++) {
            int oc = ocb + ocg*8 + 2*j + lane;
            size_t base = (((size_t)b*Cout + oc) << 10) + s0;
            float bv = bias ? bias[oc] : 0.f;
            float4 hv = make_float4(0.f, 0.f, 0.f, 0.f);
            if (hres) hv = *(const float4*)&hres[base];
            float4 ov;
            ov.x = (lane ? hi32(acc[0][j]) : lo32(acc[0][j])) + bv + hv.x;
            ov.y = (lane ? hi32(acc[1][j]) : lo32(acc[1][j])) + bv + hv.y;
            ov.z = (lane ? hi32(acc[2][j]) : lo32(acc[2][j])) + bv + hv.z;
            ov.w = (lane ? hi32(acc[3][j]) : lo32(acc[3][j])) + bv + hv.w;
            *(float4*)&out[base] = ov;
        }
    }
}

// ---------------- vector quantizer (packed dot), 256 blocks x 128 thr ----------------
__global__ void vq_kernel(const float* __restrict__ z, const float* __restrict__ cb,
                          float* __restrict__ qc, int* __restrict__ hist,
                          float* __restrict__ ssep)
{
    __shared__ ull s_cb[128][32];
    __shared__ float s_cn[128];
    __shared__ int s_hist[512];
    __shared__ float s_red[128];
    int tid = threadIdx.x;
    for (int i = tid; i < 512; i += 128) s_hist[i] = 0;

    int n = blockIdx.x * 128 + tid;
    int b = n >> 10, s = n & 1023;
    ull zp[32];
    float zv[64];
#pragma unroll
    for (int d = 0; d < 64; d++) zv[d] = z[(((size_t)b * 64 + d) << 10) + s];
#pragma unroll
    for (int j = 0; j < 32; j++) zp[j] = pack2(zv[2*j], zv[2*j+1]);

    const ull* cbu = (const ull*)cb;
    float best = 3.4e38f; int bi = 0;
    for (int k0 = 0; k0 < 512; k0 += 128) {
        __syncthreads();
        for (int i = tid; i < 128*32; i += 128)
            s_cb[i >> 5][i & 31] = cbu[((size_t)k0 << 5) + i];
        __syncthreads();
        {
            float cn = 0.f;
#pragma unroll
            for (int j = 0; j < 32; j++) {
                ull p = s_cb[tid][j];
                float a = lo32(p), bb = hi32(p);
                cn += a*a + bb*bb;
            }
            s_cn[tid] = cn;
        }
        __syncthreads();
        for (int k = 0; k < 128; k++) {
            ull dp = 0ull;
#pragma unroll
            for (int j = 0; j < 32; j++) ffma2(dp, zp[j], s_cb[k][j]);
            float dot = lo32(dp) + hi32(dp);
            float dd = s_cn[k] - 2.f * dot;
            if (dd < best) { best = dd; bi = k0 + k; }
        }
    }
    float sq = 0.f;
    const float* c = cb + ((size_t)bi << 6);
#pragma unroll
    for (int d = 0; d < 64; d++) {
        float cv = c[d];
        qc[(((size_t)b * 64 + d) << 10) + s] = cv;
        float df = cv - zv[d];
        sq += df * df;
    }
    atomicAdd(&s_hist[bi], 1);
    s_red[tid] = sq;
    __syncthreads();
    for (int st = 64; st > 0; st >>= 1) {
        if (tid < st) s_red[tid] += s_red[tid + st];
        __syncthreads();
    }
    if (tid == 0) ssep[blockIdx.x] = s_red[0];
    for (int i = tid; i < 512; i += 128)
        if (s_hist[i]) atomicAdd(&hist[i], s_hist[i]);
}

// ---------------- dt1: convT k=4 s=2 p=1 packed (in 32x32 -> out 64x64) ----------------
// weights oc-major: w[(oc*Cin + ci)*16 + k]  (OIHW, validated)
__global__ void __launch_bounds__(256, 3)
convt_f2_kernel(const float* __restrict__ in, const float* __restrict__ w,
                const float* __restrict__ bias, float* __restrict__ out,
                int Cin, int Cout)
{
    __shared__ float s_in[8][10][20];
    __shared__ ull s_w[8][16][16];
    int tid = threadIdx.x;
    int pos = tid & 31, ocg = tid >> 5;
    int posx = pos & 3, posy = pos >> 2;
    int col0 = posx * 8, row0 = posy * 2;
    int tx = blockIdx.x & 1, ty = blockIdx.x >> 1;
    int cx0 = tx * 32, ry0 = ty * 16;
    int ocb = blockIdx.y * 32;
    int b = blockIdx.z;
    ull acc[2][8][2];
#pragma unroll
    for (int r = 0; r < 2; r++)
#pragma unroll
        for (int c = 0; c < 8; c++)
#pragma unroll
            for (int j = 0; j < 2; j++) acc[r][c][j] = 0ull;

    float* swf = (float*)s_w;
    for (int c0 = 0; c0 < Cin; c0 += 8) {
        for (int i = tid; i < 8*10*18; i += 256) {
            int ci = i / 180; int rr = (i / 18) % 10; int cc = i % 18;
            int gy = (ry0 >> 1) - 1 + rr, gx = (cx0 >> 1) - 1 + cc;
            float v = 0.f;
            if ((unsigned)gy < 32u && (unsigned)gx < 32u)
                v = fmaxf(in[((b*Cin + c0 + ci)*32 + gy)*32 + gx], 0.f);
            s_in[ci][rr][cc] = v;
        }
        for (int i = tid; i < 32*128; i += 256) {
            int ocl = i >> 7; int t = i & 127; int ci = t >> 4; int k = t & 15;
            swf[(ci*16 + k)*32 + ocl] = w[((size_t)(ocb + ocl)*Cin + c0 + ci)*16 + k];
        }
        __syncthreads();
#pragma unroll
        for (int ci = 0; ci < 8; ci++) {
            ull vb[3][6];
#pragma unroll
            for (int rr = 0; rr < 3; rr++)
#pragma unroll
                for (int cc = 0; cc < 6; cc++)
                    vb[rr][cc] = bc2(s_in[ci][posy + rr][posx*4 + cc]);
#pragma unroll
            for (int r = 0; r < 2; r++) {
#pragma unroll
                for (int kxp = 0; kxp < 2; kxp++) {
                    ull wr[4][2];
                    int t0 = r*4 + kxp, t2 = (r+2)*4 + kxp;
#pragma unroll
                    for (int j = 0; j < 2; j++) {
                        wr[0][j] = s_w[ci][t0][ocg*2 + j];
                        wr[1][j] = s_w[ci][t0+2][ocg*2 + j];
                        wr[2][j] = s_w[ci][t2][ocg*2 + j];
                        wr[3][j] = s_w[ci][t2+2][ocg*2 + j];
                    }
#pragma unroll
                    for (int cs = 0; cs < 4; cs++) {
                        int c = 2*cs + kxp;
                        int cq = cs + kxp;
#pragma unroll
                        for (int j = 0; j < 2; j++) {
                            ffma2(acc[r][c][j], vb[r][cq],     wr[0][j]);
                            ffma2(acc[r][c][j], vb[r][cq+1],   wr[1][j]);
                            ffma2(acc[r][c][j], vb[r+1][cq],   wr[2][j]);
                            ffma2(acc[r][c][j], vb[r+1][cq+1], wr[3][j]);
                        }
                    }
                }
            }
        }
        __syncthreads();
    }
#pragma unroll
    for (int r = 0; r < 2; r++)
#pragma unroll
        for (int c = 0; c < 8; c++)
#pragma unroll
            for (int j = 0; j < 2; j++) {
                int oc = ocb + ocg*4 + 2*j;
                int oy = ry0 + row0 + r, ox = cx0 + col0 + c;
                float v0 = fmaxf(lo32(acc[r][c][j]) + bias[oc], 0.f);
                float v1 = fmaxf(hi32(acc[r][c][j]) + bias[oc+1], 0.f);
                out[(((size_t)b*Cout + oc)*64 + oy)*64 + ox] = v0;
                out[(((size_t)b*Cout + oc+1)*64 + oy)*64 + ox] = v1;
            }
}

// ---------------- dt2: convT k=4 s=2 p=1 scalar (64->3, out 128x128) ----------------
__global__ void convt4s2_kernel(const float* __restrict__ in, const float* __restrict__ w,
                                const float* __restrict__ bias, float* __restrict__ out,
                                int Cin, int Hin, int Win, int Cout, int inRelu, int outRelu)
{
    __shared__ float s_in[8][10][12];
    __shared__ float s_w[8][8][16];
    int tid = threadIdx.x;
    int Hout = Hin * 2, Wout = Win * 2;
    int ntx = Wout >> 4;
    int ox0 = (blockIdx.x % ntx) << 4, oy0 = (blockIdx.x / ntx) << 4;
    int ocb = blockIdx.y << 3;
    int b = blockIdx.z;
    int px = tid & 15, py = tid >> 4;
    int iy0 = oy0 >> 1, ix0 = ox0 >> 1;
    float acc[8];
#pragma unroll
    for (int i = 0; i < 8; i++) acc[i] = 0.f;

    for (int c0 = 0; c0 < Cin; c0 += 8) {
        for (int i = tid; i < 8 * 10 * 10; i += 256) {
            int ci = i / 100; int rr = (i / 10) % 10; int col = i % 10;
            int gy = iy0 - 1 + rr, gx = ix0 - 1 + col;
            float v = 0.f;
            if ((unsigned)gy < (unsigned)Hin && (unsigned)gx < (unsigned)Win)
                v = in[((b*Cin + c0 + ci)*Hin + gy)*Win + gx];
            if (inRelu) v = fmaxf(v, 0.f);
            s_in[ci][rr][col] = v;
        }
        for (int i = tid; i < 8 * 8 * 16; i += 256) {
            int oc = i >> 7; int ci = (i >> 4) & 7; int k = i & 15;
            int oco = ocb + oc;
            s_w[oc][ci][k] = (oco < Cout) ? w[((size_t)oco * Cin + c0 + ci)*16 + k] : 0.f;
        }
        __syncthreads();
        int ky0 = py & 1, kx0 = px & 1;
        int r0 = (py + ky0) >> 1;
        int q0 = (px + kx0) >> 1;
#pragma unroll
        for (int ci = 0; ci < 8; ci++) {
            float v00 = s_in[ci][r0][q0];
            float v01 = s_in[ci][r0][q0 + 1];
            float v10 = s_in[ci][r0 + 1][q0];
            float v11 = s_in[ci][r0 + 1][q0 + 1];
#pragma unroll
            for (int oc = 0; oc < 8; oc++) {
                float a = acc[oc];
                a += v00 * s_w[oc][ci][ky0*4 + kx0];
                a += v01 * s_w[oc][ci][ky0*4 + kx0 + 2];
                a += v10 * s_w[oc][ci][(ky0+2)*4 + kx0];
                a += v11 * s_w[oc][ci][(ky0+2)*4 + kx0 + 2];
                acc[oc] = a;
            }
        }
        __syncthreads();
    }
#pragma unroll
    for (int oc = 0; oc < 8; oc++) {
        int oco = ocb + oc;
        if (oco < Cout) {
            float r = acc[oc] + bias[oco];
            if (outRelu) r = fmaxf(r, 0.f);
            out[(((size_t)b * Cout + oco)*Hout + oy0 + py)*Wout + ox0 + px] = r;
        }
    }
}

// ---------------- finalize ----------------
__global__ void finalize_kernel(const int* __restrict__ hist, const float* __restrict__ ssep,
                                float* __restrict__ out, int lastIdx)
{
    __shared__ float red[512];
    __shared__ float red2[256];
    int t = threadIdx.x;
    float p = hist[t] * (1.0f / 32768.0f);
    red[t] = p * logf(p + 1e-10f);
    if (t < 256) red2[t] = ssep[t];
    __syncthreads();
    for (int st = 256; st > 0; st >>= 1) {
        if (t < st) red[t] += red[t + st];
        __syncthreads();
    }
    for (int st = 128; st > 0; st >>= 1) {
        if (t < st) red2[t] += red2[t + st];
        __syncthreads();
    }
    if (t == 0) {
        out[0] = red2[0] * 1.25f / (32768.0f * 64.0f);
        out[lastIdx] = expf(-red[0]);
    }
}

// ---------------- launch ----------------
extern "C" void kernel_launch(void* const* d_in, const int* in_sizes, int n_in,
                              void* d_out, int out_size)
{
    const float* x     = (const float*)d_in[0];
    const float* e_w1  = (const float*)d_in[1];
    const float* e_b1  = (const float*)d_in[2];
    const float* e_w2  = (const float*)d_in[3];
    const float* e_b2  = (const float*)d_in[4];
    const float* e_w3  = (const float*)d_in[5];
    const float* e_b3  = (const float*)d_in[6];
    const float* e_r1a = (const float*)d_in[7];
    const float* e_r1b = (const float*)d_in[8];
    const float* e_r2a = (const float*)d_in[9];
    const float* e_r2b = (const float*)d_in[10];
    const float* pre_w = (const float*)d_in[11];
    const float* pre_b = (const float*)d_in[12];
    const float* cb    = (const float*)d_in[13];
    const float* d_w1  = (const float*)d_in[14];
    const float* d_b1  = (const float*)d_in[15];
    const float* d_r1a = (const float*)d_in[16];
    const float* d_r1b = (const float*)d_in[17];
    const float* d_r2a = (const float*)d_in[18];
    const float* d_r2b = (const float*)d_in[19];
    const float* dt_w1 = (const float*)d_in[20];
    const float* dt_b1 = (const float*)d_in[21];
    const float* dt_w2 = (const float*)d_in[22];
    const float* dt_b2 = (const float*)d_in[23];
    float* out = (float*)d_out;

    float *A, *Bb, *C, *R, *Z, *Q, *ssep; int* hist;
    cudaGetSymbolAddress((void**)&A,    g_A);
    cudaGetSymbolAddress((void**)&Bb,   g_B);
    cudaGetSymbolAddress((void**)&C,    g_C);
    cudaGetSymbolAddress((void**)&R,    g_R);
    cudaGetSymbolAddress((void**)&Z,    g_Z);
    cudaGetSymbolAddress((void**)&Q,    g_Q);
    cudaGetSymbolAddress((void**)&ssep, g_ssep);
    cudaGetSymbolAddress((void**)&hist, g_hist);

    zero_kernel<<<2, 256>>>(hist);

    // ---- encoder ----
    conv_k4s2_kernel<<<dim3(16, 8, BATCH), 256>>>(x, e_w1, e_b1, A, 3, 128, 128, 64, 64, 64, 1);
    convk4s2_f2_kernel<<<dim3(4, 4, BATCH), 256>>>(A, e_w2, e_b2, Bb, 64, 128);
    conv3x3_f2_kernel<8, 4><<<dim3(4, 4, BATCH), 256>>>(Bb, e_w3, e_b3, C, 128, 128, 0);
    conv3x3_f2_kernel<4, 2><<<dim3(8, 1, BATCH), 256>>>(C, e_r1a, nullptr, R, 128, 32, 1);
    conv1x1_f2_kernel<<<dim3(4, 4, BATCH), 256>>>(R, e_r1b, nullptr, C, C, 32, 128);
    conv3x3_f2_kernel<4, 2><<<dim3(8, 1, BATCH), 256>>>(C, e_r2a, nullptr, R, 128, 32, 1);
    conv1x1_f2_kernel<<<dim3(4, 4, BATCH), 256>>>(R, e_r2b, nullptr, C, C, 32, 128);
    conv1x1_f2_kernel<<<dim3(4, 2, BATCH), 256>>>(C, pre_w, pre_b, nullptr, Z, 128, 64);

    // ---- VQ ----
    vq_kernel<<<256, 128>>>(Z, cb, Q, hist, ssep);

    // ---- decoder ----
    conv3x3_f2_kernel<8, 4><<<dim3(4, 4, BATCH), 256>>>(Q, d_w1, d_b1, Bb, 64, 128, 0);
    conv3x3_f2_kernel<4, 2><<<dim3(8, 1, BATCH), 256>>>(Bb, d_r1a, nullptr, R, 128, 32, 1);
    conv1x1_f2_kernel<<<dim3(4, 4, BATCH), 256>>>(R, d_r1b, nullptr, Bb, Bb, 32, 128);
    conv3x3_f2_kernel<4, 2><<<dim3(8, 1, BATCH), 256>>>(Bb, d_r2a, nullptr, R, 128, 32, 1);
    conv1x1_f2_kernel<<<dim3(4, 4, BATCH), 256>>>(R, d_r2b, nullptr, Bb, Bb, 32, 128);
    convt_f2_kernel<<<dim3(8, 2, BATCH), 256>>>(Bb, dt_w1, dt_b1, A, 128, 64);
    convt4s2_kernel<<<dim3(64, 1, BATCH), 256>>>(A, dt_w2, dt_b2, out + 1, 64, 64, 64, 3, 0, 0);

    finalize_kernel<<<1, 512>>>(hist, ssep, out, out_size - 1);
}

// round 5
// speedup vs baseline: 1.0291x; 1.0291x over previous
#include <cuda_runtime.h>
#include <cuda_bf16.h>
#include <math.h>

typedef unsigned long long ull;

// ---------------- packed f32x2 helpers ----------------
__device__ __forceinline__ ull pack2(float lo, float hi) {
    ull r; asm("mov.b64 %0, {%1, %2};" : "=l"(r) : "f"(lo), "f"(hi)); return r;
}
__device__ __forceinline__ ull bc2(float v) { return pack2(v, v); }
__device__ __forceinline__ void ffma2(ull& d, ull a, ull b) {
    asm("fma.rn.f32x2 %0, %1, %2, %0;" : "+l"(d) : "l"(a), "l"(b));
}
__device__ __forceinline__ float lo32(ull v) { return __uint_as_float((unsigned)v); }
__device__ __forceinline__ float hi32(ull v) { return __uint_as_float((unsigned)(v >> 32)); }

// ---------------- scratch ----------------
#define BATCH 32
__device__ float g_A[BATCH*64*64*64];
__device__ float g_B[BATCH*128*32*32];
__device__ float g_C[BATCH*128*32*32];
__device__ float g_R[4*BATCH*32*32*32];   // 4 Cin-split partial buffers
__device__ float g_Z[BATCH*64*32*32];
__device__ float g_Q[BATCH*64*32*32];
__device__ int   g_hist[512];
__device__ float g_ssep[256];

#define PART_STRIDE ((size_t)BATCH*32*1024)

__global__ void zero_kernel(int* hist) {
    int t = blockIdx.x * blockDim.x + threadIdx.x;
    if (t < 512) hist[t] = 0;
}

// ---------------- conv1: k=4 s=2 p=1, Cin=3 (scalar, small) ----------------
__global__ void conv_k4s2_kernel(const float* __restrict__ in, const float* __restrict__ w,
                                 const float* __restrict__ bias, float* __restrict__ out,
                                 int Cin, int Hin, int Win, int Cout, int Hout, int Wout,
                                 int outRelu)
{
    __shared__ float s_in[8][34][36];
    __shared__ float s_w[8][8][16];
    int tid = threadIdx.x;
    int ntx = Wout >> 4;
    int tx0 = (blockIdx.x % ntx) << 4, ty0 = (blockIdx.x / ntx) << 4;
    int ocb = blockIdx.y << 3;
    int b = blockIdx.z;
    int px = tid & 15, py = tid >> 4;
    float acc[8];
#pragma unroll
    for (int i = 0; i < 8; i++) acc[i] = 0.f;

    for (int c0 = 0; c0 < Cin; c0 += 8) {
        int cc = min(8, Cin - c0);
        for (int i = tid; i < cc * 34 * 34; i += 256) {
            int ci = i / (34*34); int rr = (i / 34) % 34; int col = i % 34;
            int gy = 2*ty0 - 1 + rr, gx = 2*tx0 - 1 + col;
            float v = 0.f;
            if ((unsigned)gy < (unsigned)Hin && (unsigned)gx < (unsigned)Win)
                v = in[((b*Cin + c0 + ci)*Hin + gy)*Win + gx];
            s_in[ci][rr][col] = v;
        }
        for (int i = tid; i < 8 * cc * 16; i += 256) {
            int oc = i / (cc*16); int ci = (i / 16) % cc; int k = i & 15;
            s_w[oc][ci][k] = w[((ocb+oc)*Cin + c0 + ci)*16 + k];
        }
        __syncthreads();
        for (int ci = 0; ci < cc; ci++) {
            float v[16];
#pragma unroll
            for (int ky = 0; ky < 4; ky++)
#pragma unroll
                for (int kx = 0; kx < 4; kx++)
                    v[ky*4+kx] = s_in[ci][2*py + ky][2*px + kx];
#pragma unroll
            for (int oc = 0; oc < 8; oc++) {
                float a = acc[oc];
#pragma unroll
                for (int k = 0; k < 16; k++) a += v[k] * s_w[oc][ci][k];
                acc[oc] = a;
            }
        }
        __syncthreads();
    }
#pragma unroll
    for (int oc = 0; oc < 8; oc++) {
        float r = acc[oc] + bias[ocb + oc];
        if (outRelu) r = fmaxf(r, 0.f);
        out[((b*Cout + ocb + oc)*Hout + ty0 + py)*Wout + tx0 + px] = r;
    }
}

// ---------------- conv2: k=4 s=2 p=1 packed f32x2 (R3 version, 64 oc/block) ----------------
__global__ void __launch_bounds__(256, 2)
convk4s2_f2_kernel(const float* __restrict__ in, const float* __restrict__ w,
                   const float* __restrict__ bias, float* __restrict__ out,
                   int Cin, int Cout)
{
    __shared__ float s_in[4][18][68];
    __shared__ ull s_w[4][16][32];
    int tid = threadIdx.x;
    int pos = tid & 31, ocg = tid >> 5;
    int posx = pos & 7, posy = pos >> 3;
    int col0 = posx * 4, row0 = posy * 2;
    int ry0 = blockIdx.x * 8;
    int ocb = blockIdx.y * 64;
    int b = blockIdx.z;
    ull acc[2][4][4];
#pragma unroll
    for (int r = 0; r < 2; r++)
#pragma unroll
        for (int c = 0; c < 4; c++)
#pragma unroll
            for (int j = 0; j < 4; j++) acc[r][c][j] = 0ull;

    float* swf = (float*)s_w;
    for (int c0 = 0; c0 < Cin; c0 += 4) {
        for (int i = tid; i < 4*18*66; i += 256) {
            int ci = i / (18*66); int rr = (i / 66) % 18; int cc = i % 66;
            int gy = 2*ry0 - 1 + rr, gx = cc - 1;
            float v = 0.f;
            if ((unsigned)gy < 64u && (unsigned)gx < 64u)
                v = in[((b*Cin + c0 + ci)*64 + gy)*64 + gx];
            s_in[ci][rr][cc] = v;
        }
        for (int i = tid; i < 64*64; i += 256) {
            int ocl = i >> 6; int t = i & 63; int ci = t >> 4; int k = t & 15;
            swf[(ci*16 + k)*64 + ocl] = w[(ocb + ocl)*Cin*16 + (c0 + ci)*16 + k];
        }
        __syncthreads();
#pragma unroll
        for (int ci = 0; ci < 4; ci++) {
#pragma unroll
            for (int ky = 0; ky < 4; ky++) {
#pragma unroll
                for (int r = 0; r < 2; r++) {
                    int rr = 2*row0 + 2*r + ky;
                    ull vb[10];
#pragma unroll
                    for (int t = 0; t < 10; t++) vb[t] = bc2(s_in[ci][rr][2*col0 + t]);
#pragma unroll
                    for (int kx = 0; kx < 4; kx++) {
                        ull wr[4];
#pragma unroll
                        for (int j = 0; j < 4; j++) wr[j] = s_w[ci][ky*4+kx][ocg*4 + j];
#pragma unroll
                        for (int c = 0; c < 4; c++)
#pragma unroll
                            for (int j = 0; j < 4; j++)
                                ffma2(acc[r][c][j], vb[2*c+kx], wr[j]);
                    }
                }
            }
        }
        __syncthreads();
    }
#pragma unroll
    for (int r = 0; r < 2; r++)
#pragma unroll
        for (int c = 0; c < 4; c++)
#pragma unroll
            for (int j = 0; j < 4; j++) {
                int oc = ocb + ocg*8 + 2*j;
                int row = ry0 + row0 + r, col = col0 + c;
                float v0 = fmaxf(lo32(acc[r][c][j]) + bias[oc], 0.f);
                float v1 = fmaxf(hi32(acc[r][c][j]) + bias[oc+1], 0.f);
                out[((b*Cout + oc)*32 + row)*32 + col] = v0;
                out[((b*Cout + oc+1)*32 + row)*32 + col] = v1;
            }
}

// ---------------- conv 3x3, duplicated-input smem, 128 thr, 32 oc/block ----------------
// thread: pos=tid&31 -> 2 rows x 4 cols; ocg=tid>>5 -> 8 oc (4 pairs).
// ySelCin: blockIdx.y selects a Cin part (res-split, 32ch each, output to partial buffer).
// else   : blockIdx.y selects an oc group of 32.
__global__ void __launch_bounds__(128, 4)
conv3x3_dup_kernel(const float* __restrict__ in, const float* __restrict__ w,
                   const float* __restrict__ bias, float* __restrict__ out,
                   int CinT, int cinPer, int Cout, int inRelu, int ySelCin)
{
    __shared__ ull s_in2[8][10][35];
    __shared__ ull s_w[8][9][16];
    int tid = threadIdx.x;
    int pos = tid & 31, ocg = tid >> 5;
    int posx = pos & 7, posy = pos >> 3;
    int col0 = posx * 4, row0 = posy * 2;
    int ry0 = blockIdx.x * 8;
    int b = blockIdx.z;
    int ocb, cin0;
    float* outp = out;
    if (ySelCin) { ocb = 0; cin0 = blockIdx.y * cinPer; outp = out + blockIdx.y * PART_STRIDE; }
    else         { ocb = blockIdx.y * 32; cin0 = 0; }

    ull acc[2][4][4];
#pragma unroll
    for (int r = 0; r < 2; r++)
#pragma unroll
        for (int c = 0; c < 4; c++)
#pragma unroll
            for (int j = 0; j < 4; j++) acc[r][c][j] = 0ull;

    float* swf = (float*)s_w;
    for (int c0 = 0; c0 < cinPer; c0 += 8) {
        for (int i = tid; i < 8*10*34; i += 128) {
            int ci = i / 340; int rr = (i / 34) % 10; int cc = i % 34;
            int gy = ry0 - 1 + rr, gx = cc - 1;
            float v = 0.f;
            if ((unsigned)gy < 32u && (unsigned)gx < 32u)
                v = in[((b*CinT + cin0 + c0 + ci)*32 + gy)*32 + gx];
            if (inRelu) v = fmaxf(v, 0.f);
            s_in2[ci][rr][cc] = bc2(v);
        }
        for (int i = tid; i < 32*72; i += 128) {
            int ocl = i / 72; int t = i % 72; int ci = t / 9; int k = t % 9;
            swf[(ci*9 + k)*32 + ocl] = w[(ocb + ocl)*CinT*9 + (cin0 + c0 + ci)*9 + k];
        }
        __syncthreads();
#pragma unroll 2
        for (int ci = 0; ci < 8; ci++) {
#pragma unroll
            for (int ky = 0; ky < 3; ky++) {
                ull vb0[6], vb1[6];
#pragma unroll
                for (int c = 0; c < 6; c++) {
                    vb0[c] = s_in2[ci][row0 + ky][col0 + c];
                    vb1[c] = s_in2[ci][row0 + ky + 1][col0 + c];
                }
#pragma unroll
                for (int kx = 0; kx < 3; kx++) {
                    ull wr[4];
#pragma unroll
                    for (int j = 0; j < 4; j++) wr[j] = s_w[ci][ky*3+kx][ocg*4 + j];
#pragma unroll
                    for (int c = 0; c < 4; c++)
#pragma unroll
                        for (int j = 0; j < 4; j++) {
                            ffma2(acc[0][c][j], vb0[c+kx], wr[j]);
                            ffma2(acc[1][c][j], vb1[c+kx], wr[j]);
                        }
                }
            }
        }
        __syncthreads();
    }
#pragma unroll
    for (int r = 0; r < 2; r++)
#pragma unroll
        for (int c = 0; c < 4; c++)
#pragma unroll
            for (int j = 0; j < 4; j++) {
                int oc = ocb + ocg*8 + 2*j;
                int row = ry0 + row0 + r, col = col0 + c;
                float b0 = bias ? bias[oc] : 0.f;
                float b1 = bias ? bias[oc+1] : 0.f;
                outp[((b*Cout + oc)*32 + row)*32 + col] = lo32(acc[r][c][j]) + b0;
                outp[((b*Cout + oc+1)*32 + row)*32 + col] = hi32(acc[r][c][j]) + b1;
            }
}

// ---------------- conv 1x1 packed: relu(sum of nparts partials) @ w, +bias, +res ----------------
__global__ void __launch_bounds__(256, 3)
conv1x1_f2_kernel(const float* __restrict__ in, const float* __restrict__ w,
                  const float* __restrict__ bias, const float* __restrict__ hres,
                  float* __restrict__ out, int Cin, int Cout, int nparts)
{
    __shared__ ull s_w[128][16];
    int tid = threadIdx.x;
    int pos = tid & 63, ocg = tid >> 6;
    int s0 = blockIdx.x * 256 + pos * 4;
    int ocb = blockIdx.y * 32;
    int b = blockIdx.z;
    float* swf = (float*)s_w;
    for (int i = tid; i < Cin * 32; i += 256) {
        int ocl = i / Cin; int ci = i % Cin;
        swf[ci*32 + ocl] = w[(ocb + ocl)*Cin + ci];
    }
    __syncthreads();
    ull acc[4][4];
#pragma unroll
    for (int p = 0; p < 4; p++)
#pragma unroll
        for (int j = 0; j < 4; j++) acc[p][j] = 0ull;

    for (int ci = 0; ci < Cin; ci++) {
        size_t base0 = ((size_t)(b*Cin + ci) << 10) + s0;
        float4 iv = *(const float4*)&in[base0];
        for (int p = 1; p < nparts; p++) {
            float4 t = *(const float4*)&in[p*PART_STRIDE + base0];
            iv.x += t.x; iv.y += t.y; iv.z += t.z; iv.w += t.w;
        }
        ull b0 = bc2(fmaxf(iv.x, 0.f)), b1 = bc2(fmaxf(iv.y, 0.f));
        ull b2 = bc2(fmaxf(iv.z, 0.f)), b3 = bc2(fmaxf(iv.w, 0.f));
        ull wr[4];
#pragma unroll
        for (int j = 0; j < 4; j++) wr[j] = s_w[ci][ocg*4 + j];
#pragma unroll
        for (int j = 0; j < 4; j++) {
            ffma2(acc[0][j], b0, wr[j]);
            ffma2(acc[1][j], b1, wr[j]);
            ffma2(acc[2][j], b2, wr[j]);
            ffma2(acc[3][j], b3, wr[j]);
        }
    }
#pragma unroll
    for (int j = 0; j < 4; j++) {
#pragma unroll
        for (int lane = 0; lane < 2; lane++) {
            int oc = ocb + ocg*8 + 2*j + lane;
            size_t base = (((size_t)b*Cout + oc) << 10) + s0;
            float bv = bias ? bias[oc] : 0.f;
            float4 hv = make_float4(0.f, 0.f, 0.f, 0.f);
            if (hres) hv = *(const float4*)&hres[base];
            float4 ov;
            ov.x = (lane ? hi32(acc[0][j]) : lo32(acc[0][j])) + bv + hv.x;
            ov.y = (lane ? hi32(acc[1][j]) : lo32(acc[1][j])) + bv + hv.y;
            ov.z = (lane ? hi32(acc[2][j]) : lo32(acc[2][j])) + bv + hv.z;
            ov.w = (lane ? hi32(acc[3][j]) : lo32(acc[3][j])) + bv + hv.w;
            *(float4*)&out[base] = ov;
        }
    }
}

// ---------------- vector quantizer (packed dot), 256 blocks x 128 thr ----------------
__global__ void vq_kernel(const float* __restrict__ z, const float* __restrict__ cb,
                          float* __restrict__ qc, int* __restrict__ hist,
                          float* __restrict__ ssep)
{
    __shared__ ull s_cb[128][32];
    __shared__ float s_cn[128];
    __shared__ int s_hist[512];
    __shared__ float s_red[128];
    int tid = threadIdx.x;
    for (int i = tid; i < 512; i += 128) s_hist[i] = 0;

    int n = blockIdx.x * 128 + tid;
    int b = n >> 10, s = n & 1023;
    ull zp[32];
    float zv[64];
#pragma unroll
    for (int d = 0; d < 64; d++) zv[d] = z[(((size_t)b * 64 + d) << 10) + s];
#pragma unroll
    for (int j = 0; j < 32; j++) zp[j] = pack2(zv[2*j], zv[2*j+1]);

    const ull* cbu = (const ull*)cb;
    float best = 3.4e38f; int bi = 0;
    for (int k0 = 0; k0 < 512; k0 += 128) {
        __syncthreads();
        for (int i = tid; i < 128*32; i += 128)
            s_cb[i >> 5][i & 31] = cbu[((size_t)k0 << 5) + i];
        __syncthreads();
        {
            float cn = 0.f;
#pragma unroll
            for (int j = 0; j < 32; j++) {
                ull p = s_cb[tid][j];
                float a = lo32(p), bb = hi32(p);
                cn += a*a + bb*bb;
            }
            s_cn[tid] = cn;
        }
        __syncthreads();
        for (int k = 0; k < 128; k++) {
            ull dp = 0ull;
#pragma unroll
            for (int j = 0; j < 32; j++) ffma2(dp, zp[j], s_cb[k][j]);
            float dot = lo32(dp) + hi32(dp);
            float dd = s_cn[k] - 2.f * dot;
            if (dd < best) { best = dd; bi = k0 + k; }
        }
    }
    float sq = 0.f;
    const float* c = cb + ((size_t)bi << 6);
#pragma unroll
    for (int d = 0; d < 64; d++) {
        float cv = c[d];
        qc[(((size_t)b * 64 + d) << 10) + s] = cv;
        float df = cv - zv[d];
        sq += df * df;
    }
    atomicAdd(&s_hist[bi], 1);
    s_red[tid] = sq;
    __syncthreads();
    for (int st = 64; st > 0; st >>= 1) {
        if (tid < st) s_red[tid] += s_red[tid + st];
        __syncthreads();
    }
    if (tid == 0) ssep[blockIdx.x] = s_red[0];
    for (int i = tid; i < 512; i += 128)
        if (s_hist[i]) atomicAdd(&hist[i], s_hist[i]);
}

// ---------------- dt1: convT k=4 s=2 p=1 packed (R3 version) ----------------
__global__ void __launch_bounds__(256, 2)
convt_f2_kernel(const float* __restrict__ in, const float* __restrict__ w,
                const float* __restrict__ bias, float* __restrict__ out,
                int Cin, int Cout)
{
    __shared__ float s_in[8][10][20];
    __shared__ ull s_w[8][16][16];
    int tid = threadIdx.x;
    int pos = tid & 31, ocg = tid >> 5;
    int posx = pos & 3, posy = pos >> 2;
    int col0 = posx * 8, row0 = posy * 2;
    int tx = blockIdx.x & 1, ty = blockIdx.x >> 1;
    int cx0 = tx * 32, ry0 = ty * 16;
    int ocb = blockIdx.y * 32;
    int b = blockIdx.z;
    ull acc[2][8][2];
#pragma unroll
    for (int r = 0; r < 2; r++)
#pragma unroll
        for (int c = 0; c < 8; c++)
#pragma unroll
            for (int j = 0; j < 2; j++) acc[r][c][j] = 0ull;

    float* swf = (float*)s_w;
    for (int c0 = 0; c0 < Cin; c0 += 8) {
        for (int i = tid; i < 8*10*18; i += 256) {
            int ci = i / 180; int rr = (i / 18) % 10; int cc = i % 18;
            int gy = (ry0 >> 1) - 1 + rr, gx = (cx0 >> 1) - 1 + cc;
            float v = 0.f;
            if ((unsigned)gy < 32u && (unsigned)gx < 32u)
                v = fmaxf(in[((b*Cin + c0 + ci)*32 + gy)*32 + gx], 0.f);
            s_in[ci][rr][cc] = v;
        }
        for (int i = tid; i < 32*128; i += 256) {
            int ocl = i >> 7; int t = i & 127; int ci = t >> 4; int k = t & 15;
            swf[(ci*16 + k)*32 + ocl] = w[((size_t)(ocb + ocl)*Cin + c0 + ci)*16 + k];
        }
        __syncthreads();
#pragma unroll
        for (int ci = 0; ci < 8; ci++) {
            ull vb[3][6];
#pragma unroll
            for (int rr = 0; rr < 3; rr++)
#pragma unroll
                for (int cc = 0; cc < 6; cc++)
                    vb[rr][cc] = bc2(s_in[ci][posy + rr][posx*4 + cc]);
#pragma unroll
            for (int r = 0; r < 2; r++) {
#pragma unroll
                for (int kxp = 0; kxp < 2; kxp++) {
                    ull wr[4][2];
                    int t0 = r*4 + kxp, t2 = (r+2)*4 + kxp;
#pragma unroll
                    for (int j = 0; j < 2; j++) {
                        wr[0][j] = s_w[ci][t0][ocg*2 + j];
                        wr[1][j] = s_w[ci][t0+2][ocg*2 + j];
                        wr[2][j] = s_w[ci][t2][ocg*2 + j];
                        wr[3][j] = s_w[ci][t2+2][ocg*2 + j];
                    }
#pragma unroll
                    for (int cs = 0; cs < 4; cs++) {
                        int c = 2*cs + kxp;
                        int cq = cs + kxp;
#pragma unroll
                        for (int j = 0; j < 2; j++) {
                            ffma2(acc[r][c][j], vb[r][cq],     wr[0][j]);
                            ffma2(acc[r][c][j], vb[r][cq+1],   wr[1][j]);
                            ffma2(acc[r][c][j], vb[r+1][cq],   wr[2][j]);
                            ffma2(acc[r][c][j], vb[r+1][cq+1], wr[3][j]);
                        }
                    }
                }
            }
        }
        __syncthreads();
    }
#pragma unroll
    for (int r = 0; r < 2; r++)
#pragma unroll
        for (int c = 0; c < 8; c++)
#pragma unroll
            for (int j = 0; j < 2; j++) {
                int oc = ocb + ocg*4 + 2*j;
                int oy = ry0 + row0 + r, ox = cx0 + col0 + c;
                float v0 = fmaxf(lo32(acc[r][c][j]) + bias[oc], 0.f);
                float v1 = fmaxf(hi32(acc[r][c][j]) + bias[oc+1], 0.f);
                out[(((size_t)b*Cout + oc)*64 + oy)*64 + ox] = v0;
                out[(((size_t)b*Cout + oc+1)*64 + oy)*64 + ox] = v1;
            }
}

// ---------------- dt2: convT k=4 s=2 p=1 scalar (64->3, out 128x128) ----------------
__global__ void convt4s2_kernel(const float* __restrict__ in, const float* __restrict__ w,
                                const float* __restrict__ bias, float* __restrict__ out,
                                int Cin, int Hin, int Win, int Cout, int inRelu, int outRelu)
{
    __shared__ float s_in[8][10][12];
    __shared__ float s_w[8][8][16];
    int tid = threadIdx.x;
    int Hout = Hin * 2, Wout = Win * 2;
    int ntx = Wout >> 4;
    int ox0 = (blockIdx.x % ntx) << 4, oy0 = (blockIdx.x / ntx) << 4;
    int ocb = blockIdx.y << 3;
    int b = blockIdx.z;
    int px = tid & 15, py = tid >> 4;
    int iy0 = oy0 >> 1, ix0 = ox0 >> 1;
    float acc[8];
#pragma unroll
    for (int i = 0; i < 8; i++) acc[i] = 0.f;

    for (int c0 = 0; c0 < Cin; c0 += 8) {
        for (int i = tid; i < 8 * 10 * 10; i += 256) {
            int ci = i / 100; int rr = (i / 10) % 10; int col = i % 10;
            int gy = iy0 - 1 + rr, gx = ix0 - 1 + col;
            float v = 0.f;
            if ((unsigned)gy < (unsigned)Hin && (unsigned)gx < (unsigned)Win)
                v = in[((b*Cin + c0 + ci)*Hin + gy)*Win + gx];
            if (inRelu) v = fmaxf(v, 0.f);
            s_in[ci][rr][col] = v;
        }
        for (int i = tid; i < 8 * 8 * 16; i += 256) {
            int oc = i >> 7; int ci = (i >> 4) & 7; int k = i & 15;
            int oco = ocb + oc;
            s_w[oc][ci][k] = (oco < Cout) ? w[((size_t)oco * Cin + c0 + ci)*16 + k] : 0.f;
        }
        __syncthreads();
        int ky0 = py & 1, kx0 = px & 1;
        int r0 = (py + ky0) >> 1;
        int q0 = (px + kx0) >> 1;
#pragma unroll
        for (int ci = 0; ci < 8; ci++) {
            float v00 = s_in[ci][r0][q0];
            float v01 = s_in[ci][r0][q0 + 1];
            float v10 = s_in[ci][r0 + 1][q0];
            float v11 = s_in[ci][r0 + 1][q0 + 1];
#pragma unroll
            for (int oc = 0; oc < 8; oc++) {
                float a = acc[oc];
                a += v00 * s_w[oc][ci][ky0*4 + kx0];
                a += v01 * s_w[oc][ci][ky0*4 + kx0 + 2];
                a += v10 * s_w[oc][ci][(ky0+2)*4 + kx0];
                a += v11 * s_w[oc][ci][(ky0+2)*4 + kx0 + 2];
                acc[oc] = a;
            }
        }
        __syncthreads();
    }
#pragma unroll
    for (int oc = 0; oc < 8; oc++) {
        int oco = ocb + oc;
        if (oco < Cout) {
            float r = acc[oc] + bias[oco];
            if (outRelu) r = fmaxf(r, 0.f);
            out[(((size_t)b * Cout + oco)*Hout + oy0 + py)*Wout + ox0 + px] = r;
        }
    }
}

// ---------------- finalize ----------------
__global__ void finalize_kernel(const int* __restrict__ hist, const float* __restrict__ ssep,
                                float* __restrict__ out, int lastIdx)
{
    __shared__ float red[512];
    __shared__ float red2[256];
    int t = threadIdx.x;
    float p = hist[t] * (1.0f / 32768.0f);
    red[t] = p * logf(p + 1e-10f);
    if (t < 256) red2[t] = ssep[t];
    __syncthreads();
    for (int st = 256; st > 0; st >>= 1) {
        if (t < st) red[t] += red[t + st];
        __syncthreads();
    }
    for (int st = 128; st > 0; st >>= 1) {
        if (t < st) red2[t] += red2[t + st];
        __syncthreads();
    }
    if (t == 0) {
        out[0] = red2[0] * 1.25f / (32768.0f * 64.0f);
        out[lastIdx] = expf(-red[0]);
    }
}

// ---------------- launch ----------------
extern "C" void kernel_launch(void* const* d_in, const int* in_sizes, int n_in,
                              void* d_out, int out_size)
{
    const float* x     = (const float*)d_in[0];
    const float* e_w1  = (const float*)d_in[1];
    const float* e_b1  = (const float*)d_in[2];
    const float* e_w2  = (const float*)d_in[3];
    const float* e_b2  = (const float*)d_in[4];
    const float* e_w3  = (const float*)d_in[5];
    const float* e_b3  = (const float*)d_in[6];
    const float* e_r1a = (const float*)d_in[7];
    const float* e_r1b = (const float*)d_in[8];
    const float* e_r2a = (const float*)d_in[9];
    const float* e_r2b = (const float*)d_in[10];
    const float* pre_w = (const float*)d_in[11];
    const float* pre_b = (const float*)d_in[12];
    const float* cb    = (const float*)d_in[13];
    const float* d_w1  = (const float*)d_in[14];
    const float* d_b1  = (const float*)d_in[15];
    const float* d_r1a = (const float*)d_in[16];
    const float* d_r1b = (const float*)d_in[17];
    const float* d_r2a = (const float*)d_in[18];
    const float* d_r2b = (const float*)d_in[19];
    const float* dt_w1 = (const float*)d_in[20];
    const float* dt_b1 = (const float*)d_in[21];
    const float* dt_w2 = (const float*)d_in[22];
    const float* dt_b2 = (const float*)d_in[23];
    float* out = (float*)d_out;

    float *A, *Bb, *C, *R, *Z, *Q, *ssep; int* hist;
    cudaGetSymbolAddress((void**)&A,    g_A);
    cudaGetSymbolAddress((void**)&Bb,   g_B);
    cudaGetSymbolAddress((void**)&C,    g_C);
    cudaGetSymbolAddress((void**)&R,    g_R);
    cudaGetSymbolAddress((void**)&Z,    g_Z);
    cudaGetSymbolAddress((void**)&Q,    g_Q);
    cudaGetSymbolAddress((void**)&ssep, g_ssep);
    cudaGetSymbolAddress((void**)&hist, g_hist);

    zero_kernel<<<2, 256>>>(hist);

    // ---- encoder ----
    conv_k4s2_kernel<<<dim3(16, 8, BATCH), 256>>>(x, e_w1, e_b1, A, 3, 128, 128, 64, 64, 64, 1);
    convk4s2_f2_kernel<<<dim3(4, 2, BATCH), 256>>>(A, e_w2, e_b2, Bb, 64, 128);
    // e3: 128->128, full Cin, 4 oc-groups
    conv3x3_dup_kernel<<<dim3(4, 4, BATCH), 128>>>(Bb, e_w3, e_b3, C, 128, 128, 128, 0, 0);
    // res1: 3x3 split over 4 Cin parts -> partials, then 1x1 sums+relu
    conv3x3_dup_kernel<<<dim3(4, 4, BATCH), 128>>>(C, e_r1a, nullptr, R, 128, 32, 32, 1, 1);
    conv1x1_f2_kernel<<<dim3(4, 4, BATCH), 256>>>(R, e_r1b, nullptr, C, C, 32, 128, 4);
    conv3x3_dup_kernel<<<dim3(4, 4, BATCH), 128>>>(C, e_r2a, nullptr, R, 128, 32, 32, 1, 1);
    conv1x1_f2_kernel<<<dim3(4, 4, BATCH), 256>>>(R, e_r2b, nullptr, C, C, 32, 128, 4);
    conv1x1_f2_kernel<<<dim3(4, 2, BATCH), 256>>>(C, pre_w, pre_b, nullptr, Z, 128, 64, 1);

    // ---- VQ ----
    vq_kernel<<<256, 128>>>(Z, cb, Q, hist, ssep);

    // ---- decoder ----
    conv3x3_dup_kernel<<<dim3(4, 4, BATCH), 128>>>(Q, d_w1, d_b1, Bb, 64, 64, 128, 0, 0);
    conv3x3_dup_kernel<<<dim3(4, 4, BATCH), 128>>>(Bb, d_r1a, nullptr, R, 128, 32, 32, 1, 1);
    conv1x1_f2_kernel<<<dim3(4, 4, BATCH), 256>>>(R, d_r1b, nullptr, Bb, Bb, 32, 128, 4);
    conv3x3_dup_kernel<<<dim3(4, 4, BATCH), 128>>>(Bb, d_r2a, nullptr, R, 128, 32, 32, 1, 1);
    conv1x1_f2_kernel<<<dim3(4, 4, BATCH), 256>>>(R, d_r2b, nullptr, Bb, Bb, 32, 128, 4);
    convt_f2_kernel<<<dim3(8, 2, BATCH), 256>>>(Bb, dt_w1, dt_b1, A, 128, 64);
    convt4s2_kernel<<<dim3(64, 1, BATCH), 256>>>(A, dt_w2, dt_b2, out + 1, 64, 64, 64, 3, 0, 0);

    finalize_kernel<<<1, 512>>>(hist, ssep, out, out_size - 1);
}

// round 6
// speedup vs baseline: 1.0631x; 1.0330x over previous
#include <cuda_runtime.h>
#include <cuda_bf16.h>
#include <math.h>

typedef unsigned long long ull;

// ---------------- packed f32x2 helpers ----------------
__device__ __forceinline__ ull pack2(float lo, float hi) {
    ull r; asm("mov.b64 %0, {%1, %2};" : "=l"(r) : "f"(lo), "f"(hi)); return r;
}
__device__ __forceinline__ ull bc2(float v) { return pack2(v, v); }
__device__ __forceinline__ void ffma2(ull& d, ull a, ull b) {
    asm("fma.rn.f32x2 %0, %1, %2, %0;" : "+l"(d) : "l"(a), "l"(b));
}
__device__ __forceinline__ float lo32(ull v) { return __uint_as_float((unsigned)v); }
__device__ __forceinline__ float hi32(ull v) { return __uint_as_float((unsigned)(v >> 32)); }

// ---------------- scratch ----------------
#define BATCH 32
__device__ float g_A[BATCH*64*64*64];
__device__ float g_B[BATCH*128*32*32];
__device__ float g_C[BATCH*128*32*32];
__device__ float g_R[4*BATCH*32*32*32];   // 4 Cin-split partial buffers
__device__ float g_Z[BATCH*64*32*32];
__device__ float g_Q[BATCH*64*32*32];
__device__ int   g_hist[512];
__device__ float g_ssep[256];

#define PART_STRIDE ((size_t)BATCH*32*1024)

__global__ void zero_kernel(int* hist) {
    int t = blockIdx.x * blockDim.x + threadIdx.x;
    if (t < 512) hist[t] = 0;
}

// ---------------- conv1: k=4 s=2 p=1, Cin=3 (scalar, small) ----------------
__global__ void conv_k4s2_kernel(const float* __restrict__ in, const float* __restrict__ w,
                                 const float* __restrict__ bias, float* __restrict__ out,
                                 int Cin, int Hin, int Win, int Cout, int Hout, int Wout,
                                 int outRelu)
{
    __shared__ float s_in[8][34][36];
    __shared__ float s_w[8][8][16];
    int tid = threadIdx.x;
    int ntx = Wout >> 4;
    int tx0 = (blockIdx.x % ntx) << 4, ty0 = (blockIdx.x / ntx) << 4;
    int ocb = blockIdx.y << 3;
    int b = blockIdx.z;
    int px = tid & 15, py = tid >> 4;
    float acc[8];
#pragma unroll
    for (int i = 0; i < 8; i++) acc[i] = 0.f;

    for (int c0 = 0; c0 < Cin; c0 += 8) {
        int cc = min(8, Cin - c0);
        for (int i = tid; i < cc * 34 * 34; i += 256) {
            int ci = i / (34*34); int rr = (i / 34) % 34; int col = i % 34;
            int gy = 2*ty0 - 1 + rr, gx = 2*tx0 - 1 + col;
            float v = 0.f;
            if ((unsigned)gy < (unsigned)Hin && (unsigned)gx < (unsigned)Win)
                v = in[((b*Cin + c0 + ci)*Hin + gy)*Win + gx];
            s_in[ci][rr][col] = v;
        }
        for (int i = tid; i < 8 * cc * 16; i += 256) {
            int oc = i / (cc*16); int ci = (i / 16) % cc; int k = i & 15;
            s_w[oc][ci][k] = w[((ocb+oc)*Cin + c0 + ci)*16 + k];
        }
        __syncthreads();
        for (int ci = 0; ci < cc; ci++) {
            float v[16];
#pragma unroll
            for (int ky = 0; ky < 4; ky++)
#pragma unroll
                for (int kx = 0; kx < 4; kx++)
                    v[ky*4+kx] = s_in[ci][2*py + ky][2*px + kx];
#pragma unroll
            for (int oc = 0; oc < 8; oc++) {
                float a = acc[oc];
#pragma unroll
                for (int k = 0; k < 16; k++) a += v[k] * s_w[oc][ci][k];
                acc[oc] = a;
            }
        }
        __syncthreads();
    }
#pragma unroll
    for (int oc = 0; oc < 8; oc++) {
        float r = acc[oc] + bias[ocb + oc];
        if (outRelu) r = fmaxf(r, 0.f);
        out[((b*Cout + ocb + oc)*Hout + ty0 + py)*Wout + tx0 + px] = r;
    }
}

// ---------------- conv2: k=4 s=2 p=1 packed f32x2 (R3 version, 64 oc/block) ----------------
__global__ void __launch_bounds__(256, 2)
convk4s2_f2_kernel(const float* __restrict__ in, const float* __restrict__ w,
                   const float* __restrict__ bias, float* __restrict__ out,
                   int Cin, int Cout)
{
    __shared__ float s_in[4][18][68];
    __shared__ ull s_w[4][16][32];
    int tid = threadIdx.x;
    int pos = tid & 31, ocg = tid >> 5;
    int posx = pos & 7, posy = pos >> 3;
    int col0 = posx * 4, row0 = posy * 2;
    int ry0 = blockIdx.x * 8;
    int ocb = blockIdx.y * 64;
    int b = blockIdx.z;
    ull acc[2][4][4];
#pragma unroll
    for (int r = 0; r < 2; r++)
#pragma unroll
        for (int c = 0; c < 4; c++)
#pragma unroll
            for (int j = 0; j < 4; j++) acc[r][c][j] = 0ull;

    float* swf = (float*)s_w;
    for (int c0 = 0; c0 < Cin; c0 += 4) {
        for (int i = tid; i < 4*18*66; i += 256) {
            int ci = i / (18*66); int rr = (i / 66) % 18; int cc = i % 66;
            int gy = 2*ry0 - 1 + rr, gx = cc - 1;
            float v = 0.f;
            if ((unsigned)gy < 64u && (unsigned)gx < 64u)
                v = in[((b*Cin + c0 + ci)*64 + gy)*64 + gx];
            s_in[ci][rr][cc] = v;
        }
        for (int i = tid; i < 64*64; i += 256) {
            int ocl = i >> 6; int t = i & 63; int ci = t >> 4; int k = t & 15;
            swf[(ci*16 + k)*64 + ocl] = w[(ocb + ocl)*Cin*16 + (c0 + ci)*16 + k];
        }
        __syncthreads();
#pragma unroll
        for (int ci = 0; ci < 4; ci++) {
#pragma unroll
            for (int ky = 0; ky < 4; ky++) {
#pragma unroll
                for (int r = 0; r < 2; r++) {
                    int rr = 2*row0 + 2*r + ky;
                    ull vb[10];
#pragma unroll
                    for (int t = 0; t < 10; t++) vb[t] = bc2(s_in[ci][rr][2*col0 + t]);
#pragma unroll
                    for (int kx = 0; kx < 4; kx++) {
                        ull wr[4];
#pragma unroll
                        for (int j = 0; j < 4; j++) wr[j] = s_w[ci][ky*4+kx][ocg*4 + j];
#pragma unroll
                        for (int c = 0; c < 4; c++)
#pragma unroll
                            for (int j = 0; j < 4; j++)
                                ffma2(acc[r][c][j], vb[2*c+kx], wr[j]);
                    }
                }
            }
        }
        __syncthreads();
    }
#pragma unroll
    for (int r = 0; r < 2; r++)
#pragma unroll
        for (int c = 0; c < 4; c++)
#pragma unroll
            for (int j = 0; j < 4; j++) {
                int oc = ocb + ocg*8 + 2*j;
                int row = ry0 + row0 + r, col = col0 + c;
                float v0 = fmaxf(lo32(acc[r][c][j]) + bias[oc], 0.f);
                float v1 = fmaxf(hi32(acc[r][c][j]) + bias[oc+1], 0.f);
                out[((b*Cout + oc)*32 + row)*32 + col] = v0;
                out[((b*Cout + oc+1)*32 + row)*32 + col] = v1;
            }
}

// ---------------- unified conv 3x3: RH=16, TOC=8, 256 thr, dup-input smem ----------------
// pos=tid&63 -> 2 rows x 4 cols of a 16x32 tile; ocg=tid>>6 -> 8 oc (4 pairs).
// ySelCin=1: blockIdx.y picks a Cin part of cinPer channels; output -> partial buffer.
// ySelCin=0: blockIdx.y picks an oc group of 32; full Cin (cinPer==CinT).
__global__ void __launch_bounds__(256, 2)
conv3x3_dup16(const float* __restrict__ in, const float* __restrict__ w,
              const float* __restrict__ bias, float* __restrict__ out,
              int CinT, int cinPer, int Cout, int inRelu, int ySelCin)
{
    __shared__ ull s_in2[4][18][35];
    __shared__ ull s_w[4][9][16];
    int tid = threadIdx.x;
    int pos = tid & 63, ocg = tid >> 6;
    int posx = pos & 7, posy = pos >> 3;       // posy 0..7
    int col0 = posx * 4, row0 = posy * 2;
    int ry0 = blockIdx.x * 16;
    int b = blockIdx.z;
    int ocb, cin0;
    float* outp = out;
    if (ySelCin) { ocb = 0; cin0 = blockIdx.y * cinPer; outp = out + blockIdx.y * PART_STRIDE; }
    else         { ocb = blockIdx.y * 32; cin0 = 0; }

    ull acc[2][4][4];
#pragma unroll
    for (int r = 0; r < 2; r++)
#pragma unroll
        for (int c = 0; c < 4; c++)
#pragma unroll
            for (int j = 0; j < 4; j++) acc[r][c][j] = 0ull;

    float* swf = (float*)s_w;
    for (int c0 = 0; c0 < cinPer; c0 += 4) {
        for (int i = tid; i < 4*18*34; i += 256) {
            int ci = i / 612; int rr = (i / 34) % 18; int cc = i % 34;
            int gy = ry0 - 1 + rr, gx = cc - 1;
            float v = 0.f;
            if ((unsigned)gy < 32u && (unsigned)gx < 32u)
                v = in[((b*CinT + cin0 + c0 + ci)*32 + gy)*32 + gx];
            if (inRelu) v = fmaxf(v, 0.f);
            s_in2[ci][rr][cc] = bc2(v);
        }
        for (int i = tid; i < 32*36; i += 256) {
            int ocl = i / 36; int t = i % 36; int ci = t / 9; int k = t % 9;
            swf[(ci*9 + k)*32 + ocl] = w[(ocb + ocl)*CinT*9 + (cin0 + c0 + ci)*9 + k];
        }
        __syncthreads();
#pragma unroll
        for (int ci = 0; ci < 4; ci++) {
#pragma unroll
            for (int ky = 0; ky < 3; ky++) {
                ull vb0[6], vb1[6];
#pragma unroll
                for (int c = 0; c < 6; c++) {
                    vb0[c] = s_in2[ci][row0 + ky][col0 + c];
                    vb1[c] = s_in2[ci][row0 + ky + 1][col0 + c];
                }
#pragma unroll
                for (int kx = 0; kx < 3; kx++) {
                    ull wr[4];
#pragma unroll
                    for (int j = 0; j < 4; j++) wr[j] = s_w[ci][ky*3+kx][ocg*4 + j];
#pragma unroll
                    for (int c = 0; c < 4; c++)
#pragma unroll
                        for (int j = 0; j < 4; j++) {
                            ffma2(acc[0][c][j], vb0[c+kx], wr[j]);
                            ffma2(acc[1][c][j], vb1[c+kx], wr[j]);
                        }
                }
            }
        }
        __syncthreads();
    }
#pragma unroll
    for (int r = 0; r < 2; r++)
#pragma unroll
        for (int c = 0; c < 4; c++)
#pragma unroll
            for (int j = 0; j < 4; j++) {
                int oc = ocb + ocg*8 + 2*j;
                int row = ry0 + row0 + r, col = col0 + c;
                float b0 = bias ? bias[oc] : 0.f;
                float b1 = bias ? bias[oc+1] : 0.f;
                outp[((b*Cout + oc)*32 + row)*32 + col] = lo32(acc[r][c][j]) + b0;
                outp[((b*Cout + oc+1)*32 + row)*32 + col] = hi32(acc[r][c][j]) + b1;
            }
}

// ---------------- conv 1x1 packed: relu(sum of nparts partials) @ w, +bias, +res ----------------
__global__ void __launch_bounds__(256, 3)
conv1x1_f2_kernel(const float* __restrict__ in, const float* __restrict__ w,
                  const float* __restrict__ bias, const float* __restrict__ hres,
                  float* __restrict__ out, int Cin, int Cout, int nparts)
{
    __shared__ ull s_w[128][16];
    int tid = threadIdx.x;
    int pos = tid & 63, ocg = tid >> 6;
    int s0 = blockIdx.x * 256 + pos * 4;
    int ocb = blockIdx.y * 32;
    int b = blockIdx.z;
    float* swf = (float*)s_w;
    for (int i = tid; i < Cin * 32; i += 256) {
        int ocl = i / Cin; int ci = i % Cin;
        swf[ci*32 + ocl] = w[(ocb + ocl)*Cin + ci];
    }
    __syncthreads();
    ull acc[4][4];
#pragma unroll
    for (int p = 0; p < 4; p++)
#pragma unroll
        for (int j = 0; j < 4; j++) acc[p][j] = 0ull;

    for (int ci = 0; ci < Cin; ci++) {
        size_t base0 = ((size_t)(b*Cin + ci) << 10) + s0;
        float4 iv = *(const float4*)&in[base0];
        for (int p = 1; p < nparts; p++) {
            float4 t = *(const float4*)&in[p*PART_STRIDE + base0];
            iv.x += t.x; iv.y += t.y; iv.z += t.z; iv.w += t.w;
        }
        ull b0 = bc2(fmaxf(iv.x, 0.f)), b1 = bc2(fmaxf(iv.y, 0.f));
        ull b2 = bc2(fmaxf(iv.z, 0.f)), b3 = bc2(fmaxf(iv.w, 0.f));
        ull wr[4];
#pragma unroll
        for (int j = 0; j < 4; j++) wr[j] = s_w[ci][ocg*4 + j];
#pragma unroll
        for (int j = 0; j < 4; j++) {
            ffma2(acc[0][j], b0, wr[j]);
            ffma2(acc[1][j], b1, wr[j]);
            ffma2(acc[2][j], b2, wr[j]);
            ffma2(acc[3][j], b3, wr[j]);
        }
    }
#pragma unroll
    for (int j = 0; j < 4; j++) {
#pragma unroll
        for (int lane = 0; lane < 2; lane++) {
            int oc = ocb + ocg*8 + 2*j + lane;
            size_t base = (((size_t)b*Cout + oc) << 10) + s0;
            float bv = bias ? bias[oc] : 0.f;
            float4 hv = make_float4(0.f, 0.f, 0.f, 0.f);
            if (hres) hv = *(const float4*)&hres[base];
            float4 ov;
            ov.x = (lane ? hi32(acc[0][j]) : lo32(acc[0][j])) + bv + hv.x;
            ov.y = (lane ? hi32(acc[1][j]) : lo32(acc[1][j])) + bv + hv.y;
            ov.z = (lane ? hi32(acc[2][j]) : lo32(acc[2][j])) + bv + hv.z;
            ov.w = (lane ? hi32(acc[3][j]) : lo32(acc[3][j])) + bv + hv.w;
            *(float4*)&out[base] = ov;
        }
    }
}

// ---------------- vector quantizer (packed dot), 256 blocks x 128 thr ----------------
__global__ void vq_kernel(const float* __restrict__ z, const float* __restrict__ cb,
                          float* __restrict__ qc, int* __restrict__ hist,
                          float* __restrict__ ssep)
{
    __shared__ ull s_cb[128][32];
    __shared__ float s_cn[128];
    __shared__ int s_hist[512];
    __shared__ float s_red[128];
    int tid = threadIdx.x;
    for (int i = tid; i < 512; i += 128) s_hist[i] = 0;

    int n = blockIdx.x * 128 + tid;
    int b = n >> 10, s = n & 1023;
    ull zp[32];
    float zv[64];
#pragma unroll
    for (int d = 0; d < 64; d++) zv[d] = z[(((size_t)b * 64 + d) << 10) + s];
#pragma unroll
    for (int j = 0; j < 32; j++) zp[j] = pack2(zv[2*j], zv[2*j+1]);

    const ull* cbu = (const ull*)cb;
    float best = 3.4e38f; int bi = 0;
    for (int k0 = 0; k0 < 512; k0 += 128) {
        __syncthreads();
        for (int i = tid; i < 128*32; i += 128)
            s_cb[i >> 5][i & 31] = cbu[((size_t)k0 << 5) + i];
        __syncthreads();
        {
            float cn = 0.f;
#pragma unroll
            for (int j = 0; j < 32; j++) {
                ull p = s_cb[tid][j];
                float a = lo32(p), bb = hi32(p);
                cn += a*a + bb*bb;
            }
            s_cn[tid] = cn;
        }
        __syncthreads();
        for (int k = 0; k < 128; k++) {
            ull dp = 0ull;
#pragma unroll
            for (int j = 0; j < 32; j++) ffma2(dp, zp[j], s_cb[k][j]);
            float dot = lo32(dp) + hi32(dp);
            float dd = s_cn[k] - 2.f * dot;
            if (dd < best) { best = dd; bi = k0 + k; }
        }
    }
    float sq = 0.f;
    const float* c = cb + ((size_t)bi << 6);
#pragma unroll
    for (int d = 0; d < 64; d++) {
        float cv = c[d];
        qc[(((size_t)b * 64 + d) << 10) + s] = cv;
        float df = cv - zv[d];
        sq += df * df;
    }
    atomicAdd(&s_hist[bi], 1);
    s_red[tid] = sq;
    __syncthreads();
    for (int st = 64; st > 0; st >>= 1) {
        if (tid < st) s_red[tid] += s_red[tid + st];
        __syncthreads();
    }
    if (tid == 0) ssep[blockIdx.x] = s_red[0];
    for (int i = tid; i < 512; i += 128)
        if (s_hist[i]) atomicAdd(&hist[i], s_hist[i]);
}

// ---------------- dt1: convT k=4 s=2 p=1 packed, dup-input smem ----------------
// weights oc-major: w[(oc*Cin + ci)*16 + k]  (OIHW, validated)
__global__ void __launch_bounds__(256, 2)
convt_f2_kernel(const float* __restrict__ in, const float* __restrict__ w,
                const float* __restrict__ bias, float* __restrict__ out,
                int Cin, int Cout)
{
    __shared__ ull s_in2[8][10][20];
    __shared__ ull s_w[8][16][16];
    int tid = threadIdx.x;
    int pos = tid & 31, ocg = tid >> 5;
    int posx = pos & 3, posy = pos >> 2;
    int col0 = posx * 8, row0 = posy * 2;
    int tx = blockIdx.x & 1, ty = blockIdx.x >> 1;
    int cx0 = tx * 32, ry0 = ty * 16;
    int ocb = blockIdx.y * 32;
    int b = blockIdx.z;
    ull acc[2][8][2];
#pragma unroll
    for (int r = 0; r < 2; r++)
#pragma unroll
        for (int c = 0; c < 8; c++)
#pragma unroll
            for (int j = 0; j < 2; j++) acc[r][c][j] = 0ull;

    float* swf = (float*)s_w;
    for (int c0 = 0; c0 < Cin; c0 += 8) {
        for (int i = tid; i < 8*10*18; i += 256) {
            int ci = i / 180; int rr = (i / 18) % 10; int cc = i % 18;
            int gy = (ry0 >> 1) - 1 + rr, gx = (cx0 >> 1) - 1 + cc;
            float v = 0.f;
            if ((unsigned)gy < 32u && (unsigned)gx < 32u)
                v = fmaxf(in[((b*Cin + c0 + ci)*32 + gy)*32 + gx], 0.f);
            s_in2[ci][rr][cc] = bc2(v);
        }
        for (int i = tid; i < 32*128; i += 256) {
            int ocl = i >> 7; int t = i & 127; int ci = t >> 4; int k = t & 15;
            swf[(ci*16 + k)*32 + ocl] = w[((size_t)(ocb + ocl)*Cin + c0 + ci)*16 + k];
        }
        __syncthreads();
#pragma unroll
        for (int ci = 0; ci < 8; ci++) {
            ull vb[3][6];
#pragma unroll
            for (int rr = 0; rr < 3; rr++)
#pragma unroll
                for (int cc = 0; cc < 6; cc++)
                    vb[rr][cc] = s_in2[ci][posy + rr][posx*4 + cc];
#pragma unroll
            for (int r = 0; r < 2; r++) {
#pragma unroll
                for (int kxp = 0; kxp < 2; kxp++) {
                    ull wr[4][2];
                    int t0 = r*4 + kxp, t2 = (r+2)*4 + kxp;
#pragma unroll
                    for (int j = 0; j < 2; j++) {
                        wr[0][j] = s_w[ci][t0][ocg*2 + j];
                        wr[1][j] = s_w[ci][t0+2][ocg*2 + j];
                        wr[2][j] = s_w[ci][t2][ocg*2 + j];
                        wr[3][j] = s_w[ci][t2+2][ocg*2 + j];
                    }
#pragma unroll
                    for (int cs = 0; cs < 4; cs++) {
                        int c = 2*cs + kxp;
                        int cq = cs + kxp;
#pragma unroll
                        for (int j = 0; j < 2; j++) {
                            ffma2(acc[r][c][j], vb[r][cq],     wr[0][j]);
                            ffma2(acc[r][c][j], vb[r][cq+1],   wr[1][j]);
                            ffma2(acc[r][c][j], vb[r+1][cq],   wr[2][j]);
                            ffma2(acc[r][c][j], vb[r+1][cq+1], wr[3][j]);
                        }
                    }
                }
            }
        }
        __syncthreads();
    }
#pragma unroll
    for (int r = 0; r < 2; r++)
#pragma unroll
        for (int c = 0; c < 8; c++)
#pragma unroll
            for (int j = 0; j < 2; j++) {
                int oc = ocb + ocg*4 + 2*j;
                int oy = ry0 + row0 + r, ox = cx0 + col0 + c;
                float v0 = fmaxf(lo32(acc[r][c][j]) + bias[oc], 0.f);
                float v1 = fmaxf(hi32(acc[r][c][j]) + bias[oc+1], 0.f);
                out[(((size_t)b*Cout + oc)*64 + oy)*64 + ox] = v0;
                out[(((size_t)b*Cout + oc+1)*64 + oy)*64 + ox] = v1;
            }
}

// ---------------- dt2: convT k=4 s=2 p=1 scalar (64->3, out 128x128), 4-oc pad ----------------
__global__ void convt4s2_kernel(const float* __restrict__ in, const float* __restrict__ w,
                                const float* __restrict__ bias, float* __restrict__ out,
                                int Cin, int Hin, int Win, int Cout, int inRelu, int outRelu)
{
    __shared__ float s_in[8][10][12];
    __shared__ float s_w[4][8][16];
    int tid = threadIdx.x;
    int Hout = Hin * 2, Wout = Win * 2;
    int ntx = Wout >> 4;
    int ox0 = (blockIdx.x % ntx) << 4, oy0 = (blockIdx.x / ntx) << 4;
    int b = blockIdx.z;
    int px = tid & 15, py = tid >> 4;
    int iy0 = oy0 >> 1, ix0 = ox0 >> 1;
    float acc[4];
#pragma unroll
    for (int i = 0; i < 4; i++) acc[i] = 0.f;

    for (int c0 = 0; c0 < Cin; c0 += 8) {
        for (int i = tid; i < 8 * 10 * 10; i += 256) {
            int ci = i / 100; int rr = (i / 10) % 10; int col = i % 10;
            int gy = iy0 - 1 + rr, gx = ix0 - 1 + col;
            float v = 0.f;
            if ((unsigned)gy < (unsigned)Hin && (unsigned)gx < (unsigned)Win)
                v = in[((b*Cin + c0 + ci)*Hin + gy)*Win + gx];
            if (inRelu) v = fmaxf(v, 0.f);
            s_in[ci][rr][col] = v;
        }
        for (int i = tid; i < 4 * 8 * 16; i += 256) {
            int oc = i >> 7; int ci = (i >> 4) & 7; int k = i & 15;
            s_w[oc][ci][k] = (oc < Cout) ? w[((size_t)oc * Cin + c0 + ci)*16 + k] : 0.f;
        }
        __syncthreads();
        int ky0 = py & 1, kx0 = px & 1;
        int r0 = (py + ky0) >> 1;
        int q0 = (px + kx0) >> 1;
#pragma unroll
        for (int ci = 0; ci < 8; ci++) {
            float v00 = s_in[ci][r0][q0];
            float v01 = s_in[ci][r0][q0 + 1];
            float v10 = s_in[ci][r0 + 1][q0];
            float v11 = s_in[ci][r0 + 1][q0 + 1];
#pragma unroll
            for (int oc = 0; oc < 4; oc++) {
                float a = acc[oc];
                a += v00 * s_w[oc][ci][ky0*4 + kx0];
                a += v01 * s_w[oc][ci][ky0*4 + kx0 + 2];
                a += v10 * s_w[oc][ci][(ky0+2)*4 + kx0];
                a += v11 * s_w[oc][ci][(ky0+2)*4 + kx0 + 2];
                acc[oc] = a;
            }
        }
        __syncthreads();
    }
#pragma unroll
    for (int oc = 0; oc < 4; oc++) {
        if (oc < Cout) {
            float r = acc[oc] + bias[oc];
            if (outRelu) r = fmaxf(r, 0.f);
            out[(((size_t)b * Cout + oc)*Hout + oy0 + py)*Wout + ox0 + px] = r;
        }
    }
}

// ---------------- finalize ----------------
__global__ void finalize_kernel(const int* __restrict__ hist, const float* __restrict__ ssep,
                                float* __restrict__ out, int lastIdx)
{
    __shared__ float red[512];
    __shared__ float red2[256];
    int t = threadIdx.x;
    float p = hist[t] * (1.0f / 32768.0f);
    red[t] = p * logf(p + 1e-10f);
    if (t < 256) red2[t] = ssep[t];
    __syncthreads();
    for (int st = 256; st > 0; st >>= 1) {
        if (t < st) red[t] += red[t + st];
        __syncthreads();
    }
    for (int st = 128; st > 0; st >>= 1) {
        if (t < st) red2[t] += red2[t + st];
        __syncthreads();
    }
    if (t == 0) {
        out[0] = red2[0] * 1.25f / (32768.0f * 64.0f);
        out[lastIdx] = expf(-red[0]);
    }
}

// ---------------- launch ----------------
extern "C" void kernel_launch(void* const* d_in, const int* in_sizes, int n_in,
                              void* d_out, int out_size)
{
    const float* x     = (const float*)d_in[0];
    const float* e_w1  = (const float*)d_in[1];
    const float* e_b1  = (const float*)d_in[2];
    const float* e_w2  = (const float*)d_in[3];
    const float* e_b2  = (const float*)d_in[4];
    const float* e_w3  = (const float*)d_in[5];
    const float* e_b3  = (const float*)d_in[6];
    const float* e_r1a = (const float*)d_in[7];
    const float* e_r1b = (const float*)d_in[8];
    const float* e_r2a = (const float*)d_in[9];
    const float* e_r2b = (const float*)d_in[10];
    const float* pre_w = (const float*)d_in[11];
    const float* pre_b = (const float*)d_in[12];
    const float* cb    = (const float*)d_in[13];
    const float* d_w1  = (const float*)d_in[14];
    const float* d_b1  = (const float*)d_in[15];
    const float* d_r1a = (const float*)d_in[16];
    const float* d_r1b = (const float*)d_in[17];
    const float* d_r2a = (const float*)d_in[18];
    const float* d_r2b = (const float*)d_in[19];
    const float* dt_w1 = (const float*)d_in[20];
    const float* dt_b1 = (const float*)d_in[21];
    const float* dt_w2 = (const float*)d_in[22];
    const float* dt_b2 = (const float*)d_in[23];
    float* out = (float*)d_out;

    float *A, *Bb, *C, *R, *Z, *Q, *ssep; int* hist;
    cudaGetSymbolAddress((void**)&A,    g_A);
    cudaGetSymbolAddress((void**)&Bb,   g_B);
    cudaGetSymbolAddress((void**)&C,    g_C);
    cudaGetSymbolAddress((void**)&R,    g_R);
    cudaGetSymbolAddress((void**)&Z,    g_Z);
    cudaGetSymbolAddress((void**)&Q,    g_Q);
    cudaGetSymbolAddress((void**)&ssep, g_ssep);
    cudaGetSymbolAddress((void**)&hist, g_hist);

    zero_kernel<<<2, 256>>>(hist);

    // ---- encoder ----
    conv_k4s2_kernel<<<dim3(16, 8, BATCH), 256>>>(x, e_w1, e_b1, A, 3, 128, 128, 64, 64, 64, 1);
    convk4s2_f2_kernel<<<dim3(4, 2, BATCH), 256>>>(A, e_w2, e_b2, Bb, 64, 128);
    // e3: 128->128, full Cin, 4 oc-groups of 32
    conv3x3_dup16<<<dim3(2, 4, BATCH), 256>>>(Bb, e_w3, e_b3, C, 128, 128, 128, 0, 0);
    // res1: 3x3 Cin-split 4 ways -> partials; 1x1 sums 4 partials + relu
    conv3x3_dup16<<<dim3(2, 4, BATCH), 256>>>(C, e_r1a, nullptr, R, 128, 32, 32, 1, 1);
    conv1x1_f2_kernel<<<dim3(4, 4, BATCH), 256>>>(R, e_r1b, nullptr, C, C, 32, 128, 4);
    conv3x3_dup16<<<dim3(2, 4, BATCH), 256>>>(C, e_r2a, nullptr, R, 128, 32, 32, 1, 1);
    conv1x1_f2_kernel<<<dim3(4, 4, BATCH), 256>>>(R, e_r2b, nullptr, C, C, 32, 128, 4);
    conv1x1_f2_kernel<<<dim3(4, 2, BATCH), 256>>>(C, pre_w, pre_b, nullptr, Z, 128, 64, 1);

    // ---- VQ ----
    vq_kernel<<<256, 128>>>(Z, cb, Q, hist, ssep);

    // ---- decoder ----
    conv3x3_dup16<<<dim3(2, 4, BATCH), 256>>>(Q, d_w1, d_b1, Bb, 64, 64, 128, 0, 0);
    conv3x3_dup16<<<dim3(2, 4, BATCH), 256>>>(Bb, d_r1a, nullptr, R, 128, 32, 32, 1, 1);
    conv1x1_f2_kernel<<<dim3(4, 4, BATCH), 256>>>(R, d_r1b, nullptr, Bb, Bb, 32, 128, 4);
    conv3x3_dup16<<<dim3(2, 4, BATCH), 256>>>(Bb, d_r2a, nullptr, R, 128, 32, 32, 1, 1);
    conv1x1_f2_kernel<<<dim3(4, 4, BATCH), 256>>>(R, d_r2b, nullptr, Bb, Bb, 32, 128, 4);
    convt_f2_kernel<<<dim3(8, 2, BATCH), 256>>>(Bb, dt_w1, dt_b1, A, 128, 64);
    convt4s2_kernel<<<dim3(64, 1, BATCH), 256>>>(A, dt_w2, dt_b2, out + 1, 64, 64, 64, 3, 0, 0);

    finalize_kernel<<<1, 512>>>(hist, ssep, out, out_size - 1);
}

// round 7
// speedup vs baseline: 1.1426x; 1.0748x over previous
#include <cuda_runtime.h>
#include <cuda_bf16.h>
#include <math.h>

typedef unsigned long long ull;

__device__ __forceinline__ ull pack2(float lo, float hi) {
    ull r; asm("mov.b64 %0, {%1, %2};" : "=l"(r) : "f"(lo), "f"(hi)); return r;
}
__device__ __forceinline__ ull bc2(float v) { return pack2(v, v); }
__device__ __forceinline__ void ffma2(ull& d, ull a, ull b) {
    asm("fma.rn.f32x2 %0, %1, %2, %0;" : "+l"(d) : "l"(a), "l"(b));
}
__device__ __forceinline__ float lo32(ull v) { return __uint_as_float((unsigned)v); }
__device__ __forceinline__ float hi32(ull v) { return __uint_as_float((unsigned)(v >> 32)); }

#define BATCH 32
__device__ float g_A[BATCH*64*64*64];
__device__ float g_B[BATCH*128*32*32];
__device__ float g_C[BATCH*128*32*32];
__device__ float g_R[4*BATCH*32*32*32];
__device__ float g_Z[BATCH*64*32*32];
__device__ float g_Q[BATCH*64*32*32];
__device__ int   g_hist[512];
__device__ float g_ssep[256];

#define PART_STRIDE ((size_t)BATCH*32*1024)

__global__ void zero_kernel(int* hist) {
    int t = blockIdx.x * blockDim.x + threadIdx.x;
    if (t < 512) hist[t] = 0;
}

// ---------------- conv1: k=4 s=2 p=1, Cin=3 (scalar) ----------------
__global__ void conv_k4s2_kernel(const float* __restrict__ in, const float* __restrict__ w,
                                 const float* __restrict__ bias, float* __restrict__ out,
                                 int Cin, int Hin, int Win, int Cout, int Hout, int Wout,
                                 int outRelu)
{
    __shared__ float s_in[8][34][36];
    __shared__ float s_w[8][8][16];
    int tid = threadIdx.x;
    int ntx = Wout >> 4;
    int tx0 = (blockIdx.x % ntx) << 4, ty0 = (blockIdx.x / ntx) << 4;
    int ocb = blockIdx.y << 3;
    int b = blockIdx.z;
    int px = tid & 15, py = tid >> 4;
    float acc[8];
#pragma unroll
    for (int i = 0; i < 8; i++) acc[i] = 0.f;

    for (int c0 = 0; c0 < Cin; c0 += 8) {
        int cc = min(8, Cin - c0);
        for (int i = tid; i < cc * 34 * 34; i += 256) {
            int ci = i / (34*34); int rr = (i / 34) % 34; int col = i % 34;
            int gy = 2*ty0 - 1 + rr, gx = 2*tx0 - 1 + col;
            float v = 0.f;
            if ((unsigned)gy < (unsigned)Hin && (unsigned)gx < (unsigned)Win)
                v = in[((b*Cin + c0 + ci)*Hin + gy)*Win + gx];
            s_in[ci][rr][col] = v;
        }
        for (int i = tid; i < 8 * cc * 16; i += 256) {
            int oc = i / (cc*16); int ci = (i / 16) % cc; int k = i & 15;
            s_w[oc][ci][k] = w[((ocb+oc)*Cin + c0 + ci)*16 + k];
        }
        __syncthreads();
        for (int ci = 0; ci < cc; ci++) {
            float v[16];
#pragma unroll
            for (int ky = 0; ky < 4; ky++)
#pragma unroll
                for (int kx = 0; kx < 4; kx++)
                    v[ky*4+kx] = s_in[ci][2*py + ky][2*px + kx];
#pragma unroll
            for (int oc = 0; oc < 8; oc++) {
                float a = acc[oc];
#pragma unroll
                for (int k = 0; k < 16; k++) a += v[k] * s_w[oc][ci][k];
                acc[oc] = a;
            }
        }
        __syncthreads();
    }
#pragma unroll
    for (int oc = 0; oc < 8; oc++) {
        float r = acc[oc] + bias[ocb + oc];
        if (outRelu) r = fmaxf(r, 0.f);
        out[((b*Cout + ocb + oc)*Hout + ty0 + py)*Wout + tx0 + px] = r;
    }
}

// ---------------- conv2: k=4 s=2 p=1 packed (stride padded 69) ----------------
__global__ void __launch_bounds__(256, 2)
convk4s2_f2_kernel(const float* __restrict__ in, const float* __restrict__ w,
                   const float* __restrict__ bias, float* __restrict__ out,
                   int Cin, int Cout)
{
    __shared__ float s_in[4][18][69];
    __shared__ ull s_w[4][16][32];
    int tid = threadIdx.x;
    int pos = tid & 31, ocg = tid >> 5;
    int posx = pos & 7, posy = pos >> 3;
    int col0 = posx * 4, row0 = posy * 2;
    int ry0 = blockIdx.x * 8;
    int ocb = blockIdx.y * 64;
    int b = blockIdx.z;
    ull acc[2][4][4];
#pragma unroll
    for (int r = 0; r < 2; r++)
#pragma unroll
        for (int c = 0; c < 4; c++)
#pragma unroll
            for (int j = 0; j < 4; j++) acc[r][c][j] = 0ull;

    float* swf = (float*)s_w;
    for (int c0 = 0; c0 < Cin; c0 += 4) {
        for (int i = tid; i < 4*18*66; i += 256) {
            int ci = i / (18*66); int rr = (i / 66) % 18; int cc = i % 66;
            int gy = 2*ry0 - 1 + rr, gx = cc - 1;
            float v = 0.f;
            if ((unsigned)gy < 64u && (unsigned)gx < 64u)
                v = in[((b*Cin + c0 + ci)*64 + gy)*64 + gx];
            s_in[ci][rr][cc] = v;
        }
        for (int i = tid; i < 64*64; i += 256) {
            int ocl = i >> 6; int t = i & 63; int ci = t >> 4; int k = t & 15;
            swf[(ci*16 + k)*64 + ocl] = w[(ocb + ocl)*Cin*16 + (c0 + ci)*16 + k];
        }
        __syncthreads();
#pragma unroll
        for (int ci = 0; ci < 4; ci++) {
#pragma unroll
            for (int ky = 0; ky < 4; ky++) {
#pragma unroll
                for (int r = 0; r < 2; r++) {
                    int rr = 2*row0 + 2*r + ky;
                    ull vb[10];
#pragma unroll
                    for (int t = 0; t < 10; t++) vb[t] = bc2(s_in[ci][rr][2*col0 + t]);
#pragma unroll
                    for (int kx = 0; kx < 4; kx++) {
                        ull wr[4];
#pragma unroll
                        for (int j = 0; j < 4; j++) wr[j] = s_w[ci][ky*4+kx][ocg*4 + j];
#pragma unroll
                        for (int c = 0; c < 4; c++)
#pragma unroll
                            for (int j = 0; j < 4; j++)
                                ffma2(acc[r][c][j], vb[2*c+kx], wr[j]);
                    }
                }
            }
        }
        __syncthreads();
    }
#pragma unroll
    for (int r = 0; r < 2; r++)
#pragma unroll
        for (int c = 0; c < 4; c++)
#pragma unroll
            for (int j = 0; j < 4; j++) {
                int oc = ocb + ocg*8 + 2*j;
                int row = ry0 + row0 + r, col = col0 + c;
                float v0 = fmaxf(lo32(acc[r][c][j]) + bias[oc], 0.f);
                float v1 = fmaxf(hi32(acc[r][c][j]) + bias[oc+1], 0.f);
                out[((b*Cout + oc)*32 + row)*32 + col] = v0;
                out[((b*Cout + oc+1)*32 + row)*32 + col] = v1;
            }
}

// ---- unified conv3x3: RH=16, TOC=8, 256 thr, 16-ch chunks, stride-35 pad ----
// pos=tid&63 -> 2 rows x 4 cols of 16x32 tile; ocg=tid>>6 -> 8 oc.
// ySelCin=1: blockIdx.y = Cin part (cinPer ch) -> partial buffer. else oc group of 32.
__global__ void __launch_bounds__(256, 2)
conv3x3_u(const float* __restrict__ in, const float* __restrict__ w,
          const float* __restrict__ bias, float* __restrict__ out,
          int CinT, int cinPer, int Cout, int inRelu, int ySelCin)
{
    __shared__ float s_in[16][18][35];
    __shared__ ull s_w[16][9][16];
    int tid = threadIdx.x;
    int pos = tid & 63, ocg = tid >> 6;
    int posx = pos & 7, posy = pos >> 3;
    int col0 = posx * 4, row0 = posy * 2;
    int ry0 = blockIdx.x * 16;
    int b = blockIdx.z;
    int ocb, cin0;
    float* outp = out;
    if (ySelCin) { ocb = 0; cin0 = blockIdx.y * cinPer; outp = out + blockIdx.y * PART_STRIDE; }
    else         { ocb = blockIdx.y * 32; cin0 = 0; }

    ull acc[2][4][4];
#pragma unroll
    for (int r = 0; r < 2; r++)
#pragma unroll
        for (int c = 0; c < 4; c++)
#pragma unroll
            for (int j = 0; j < 4; j++) acc[r][c][j] = 0ull;

    float* swf = (float*)s_w;
    for (int c0 = 0; c0 < cinPer; c0 += 16) {
        for (int i = tid; i < 16*18*34; i += 256) {
            int ci = i / (18*34); int rr = (i / 34) % 18; int cc = i % 34;
            int gy = ry0 - 1 + rr, gx = cc - 1;
            float v = 0.f;
            if ((unsigned)gy < 32u && (unsigned)gx < 32u)
                v = in[((b*CinT + cin0 + c0 + ci)*32 + gy)*32 + gx];
            if (inRelu) v = fmaxf(v, 0.f);
            s_in[ci][rr][cc] = v;
        }
        for (int i = tid; i < 32*144; i += 256) {
            int ocl = i / 144; int t = i % 144; int ci = t / 9; int k = t % 9;
            swf[(ci*9 + k)*32 + ocl] = w[(ocb + ocl)*CinT*9 + (cin0 + c0 + ci)*9 + k];
        }
        __syncthreads();
#pragma unroll 4
        for (int ci = 0; ci < 16; ci++) {
#pragma unroll
            for (int ky = 0; ky < 3; ky++) {
                ull vb0[6], vb1[6];
#pragma unroll
                for (int c = 0; c < 6; c++) {
                    vb0[c] = bc2(s_in[ci][row0 + ky][col0 + c]);
                    vb1[c] = bc2(s_in[ci][row0 + ky + 1][col0 + c]);
                }
#pragma unroll
                for (int kx = 0; kx < 3; kx++) {
                    ull wr[4];
#pragma unroll
                    for (int j = 0; j < 4; j++) wr[j] = s_w[ci][ky*3+kx][ocg*4 + j];
#pragma unroll
                    for (int c = 0; c < 4; c++)
#pragma unroll
                        for (int j = 0; j < 4; j++) {
                            ffma2(acc[0][c][j], vb0[c+kx], wr[j]);
                            ffma2(acc[1][c][j], vb1[c+kx], wr[j]);
                        }
                }
            }
        }
        __syncthreads();
    }
#pragma unroll
    for (int r = 0; r < 2; r++)
#pragma unroll
        for (int c = 0; c < 4; c++)
#pragma unroll
            for (int j = 0; j < 4; j++) {
                int oc = ocb + ocg*8 + 2*j;
                int row = ry0 + row0 + r, col = col0 + c;
                float b0 = bias ? bias[oc] : 0.f;
                float b1 = bias ? bias[oc+1] : 0.f;
                outp[((b*Cout + oc)*32 + row)*32 + col] = lo32(acc[r][c][j]) + b0;
                outp[((b*Cout + oc+1)*32 + row)*32 + col] = hi32(acc[r][c][j]) + b1;
            }
}

// ---------------- conv 1x1: relu(sum of nparts partials) @ w, +bias, +res ----------------
__global__ void __launch_bounds__(256, 3)
conv1x1_f2_kernel(const float* __restrict__ in, const float* __restrict__ w,
                  const float* __restrict__ bias, const float* __restrict__ hres,
                  float* __restrict__ out, int Cin, int Cout, int nparts)
{
    __shared__ ull s_w[128][16];
    int tid = threadIdx.x;
    int pos = tid & 63, ocg = tid >> 6;
    int s0 = blockIdx.x * 256 + pos * 4;
    int ocb = blockIdx.y * 32;
    int b = blockIdx.z;
    float* swf = (float*)s_w;
    for (int i = tid; i < Cin * 32; i += 256) {
        int ocl = i / Cin; int ci = i % Cin;
        swf[ci*32 + ocl] = w[(ocb + ocl)*Cin + ci];
    }
    __syncthreads();
    ull acc[4][4];
#pragma unroll
    for (int p = 0; p < 4; p++)
#pragma unroll
        for (int j = 0; j < 4; j++) acc[p][j] = 0ull;

    for (int ci = 0; ci < Cin; ci++) {
        size_t base0 = ((size_t)(b*Cin + ci) << 10) + s0;
        float4 iv = *(const float4*)&in[base0];
        for (int p = 1; p < nparts; p++) {
            float4 t = *(const float4*)&in[p*PART_STRIDE + base0];
            iv.x += t.x; iv.y += t.y; iv.z += t.z; iv.w += t.w;
        }
        ull b0 = bc2(fmaxf(iv.x, 0.f)), b1 = bc2(fmaxf(iv.y, 0.f));
        ull b2 = bc2(fmaxf(iv.z, 0.f)), b3 = bc2(fmaxf(iv.w, 0.f));
        ull wr[4];
#pragma unroll
        for (int j = 0; j < 4; j++) wr[j] = s_w[ci][ocg*4 + j];
#pragma unroll
        for (int j = 0; j < 4; j++) {
            ffma2(acc[0][j], b0, wr[j]);
            ffma2(acc[1][j], b1, wr[j]);
            ffma2(acc[2][j], b2, wr[j]);
            ffma2(acc[3][j], b3, wr[j]);
        }
    }
#pragma unroll
    for (int j = 0; j < 4; j++) {
#pragma unroll
        for (int lane = 0; lane < 2; lane++) {
            int oc = ocb + ocg*8 + 2*j + lane;
            size_t base = (((size_t)b*Cout + oc) << 10) + s0;
            float bv = bias ? bias[oc] : 0.f;
            float4 hv = make_float4(0.f, 0.f, 0.f, 0.f);
            if (hres) hv = *(const float4*)&hres[base];
            float4 ov;
            ov.x = (lane ? hi32(acc[0][j]) : lo32(acc[0][j])) + bv + hv.x;
            ov.y = (lane ? hi32(acc[1][j]) : lo32(acc[1][j])) + bv + hv.y;
            ov.z = (lane ? hi32(acc[2][j]) : lo32(acc[2][j])) + bv + hv.z;
            ov.w = (lane ? hi32(acc[3][j]) : lo32(acc[3][j])) + bv + hv.w;
            *(float4*)&out[base] = ov;
        }
    }
}

// ---------------- vector quantizer ----------------
__global__ void vq_kernel(const float* __restrict__ z, const float* __restrict__ cb,
                          float* __restrict__ qc, int* __restrict__ hist,
                          float* __restrict__ ssep)
{
    __shared__ ull s_cb[128][32];
    __shared__ float s_cn[128];
    __shared__ int s_hist[512];
    __shared__ float s_red[128];
    int tid = threadIdx.x;
    for (int i = tid; i < 512; i += 128) s_hist[i] = 0;

    int n = blockIdx.x * 128 + tid;
    int b = n >> 10, s = n & 1023;
    ull zp[32];
    float zv[64];
#pragma unroll
    for (int d = 0; d < 64; d++) zv[d] = z[(((size_t)b * 64 + d) << 10) + s];
#pragma unroll
    for (int j = 0; j < 32; j++) zp[j] = pack2(zv[2*j], zv[2*j+1]);

    const ull* cbu = (const ull*)cb;
    float best = 3.4e38f; int bi = 0;
    for (int k0 = 0; k0 < 512; k0 += 128) {
        __syncthreads();
        for (int i = tid; i < 128*32; i += 128)
            s_cb[i >> 5][i & 31] = cbu[((size_t)k0 << 5) + i];
        __syncthreads();
        {
            float cn = 0.f;
#pragma unroll
            for (int j = 0; j < 32; j++) {
                ull p = s_cb[tid][j];
                float a = lo32(p), bb = hi32(p);
                cn += a*a + bb*bb;
            }
            s_cn[tid] = cn;
        }
        __syncthreads();
        for (int k = 0; k < 128; k++) {
            ull dp = 0ull;
#pragma unroll
            for (int j = 0; j < 32; j++) ffma2(dp, zp[j], s_cb[k][j]);
            float dot = lo32(dp) + hi32(dp);
            float dd = s_cn[k] - 2.f * dot;
            if (dd < best) { best = dd; bi = k0 + k; }
        }
    }
    float sq = 0.f;
    const float* c = cb + ((size_t)bi << 6);
#pragma unroll
    for (int d = 0; d < 64; d++) {
        float cv = c[d];
        qc[(((size_t)b * 64 + d) << 10) + s] = cv;
        float df = cv - zv[d];
        sq += df * df;
    }
    atomicAdd(&s_hist[bi], 1);
    s_red[tid] = sq;
    __syncthreads();
    for (int st = 64; st > 0; st >>= 1) {
        if (tid < st) s_red[tid] += s_red[tid + st];
        __syncthreads();
    }
    if (tid == 0) ssep[blockIdx.x] = s_red[0];
    for (int i = tid; i < 512; i += 128)
        if (s_hist[i]) atomicAdd(&hist[i], s_hist[i]);
}

// ---------------- dt1: convT k=4 s=2 p=1 packed (stride 21 pad) ----------------
__global__ void __launch_bounds__(256, 2)
convt_f2_kernel(const float* __restrict__ in, const float* __restrict__ w,
                const float* __restrict__ bias, float* __restrict__ out,
                int Cin, int Cout)
{
    __shared__ float s_in[8][10][21];
    __shared__ ull s_w[8][16][16];
    int tid = threadIdx.x;
    int pos = tid & 31, ocg = tid >> 5;
    int posx = pos & 3, posy = pos >> 2;
    int col0 = posx * 8, row0 = posy * 2;
    int tx = blockIdx.x & 1, ty = blockIdx.x >> 1;
    int cx0 = tx * 32, ry0 = ty * 16;
    int ocb = blockIdx.y * 32;
    int b = blockIdx.z;
    ull acc[2][8][2];
#pragma unroll
    for (int r = 0; r < 2; r++)
#pragma unroll
        for (int c = 0; c < 8; c++)
#pragma unroll
            for (int j = 0; j < 2; j++) acc[r][c][j] = 0ull;

    float* swf = (float*)s_w;
    for (int c0 = 0; c0 < Cin; c0 += 8) {
        for (int i = tid; i < 8*10*18; i += 256) {
            int ci = i / 180; int rr = (i / 18) % 10; int cc = i % 18;
            int gy = (ry0 >> 1) - 1 + rr, gx = (cx0 >> 1) - 1 + cc;
            float v = 0.f;
            if ((unsigned)gy < 32u && (unsigned)gx < 32u)
                v = fmaxf(in[((b*Cin + c0 + ci)*32 + gy)*32 + gx], 0.f);
            s_in[ci][rr][cc] = v;
        }
        for (int i = tid; i < 32*128; i += 256) {
            int ocl = i >> 7; int t = i & 127; int ci = t >> 4; int k = t & 15;
            swf[(ci*16 + k)*32 + ocl] = w[((size_t)(ocb + ocl)*Cin + c0 + ci)*16 + k];
        }
        __syncthreads();
#pragma unroll
        for (int ci = 0; ci < 8; ci++) {
            ull vb[3][6];
#pragma unroll
            for (int rr = 0; rr < 3; rr++)
#pragma unroll
                for (int cc = 0; cc < 6; cc++)
                    vb[rr][cc] = bc2(s_in[ci][posy + rr][posx*4 + cc]);
#pragma unroll
            for (int r = 0; r < 2; r++) {
#pragma unroll
                for (int kxp = 0; kxp < 2; kxp++) {
                    ull wr[4][2];
                    int t0 = r*4 + kxp, t2 = (r+2)*4 + kxp;
#pragma unroll
                    for (int j = 0; j < 2; j++) {
                        wr[0][j] = s_w[ci][t0][ocg*2 + j];
                        wr[1][j] = s_w[ci][t0+2][ocg*2 + j];
                        wr[2][j] = s_w[ci][t2][ocg*2 + j];
                        wr[3][j] = s_w[ci][t2+2][ocg*2 + j];
                    }
#pragma unroll
                    for (int cs = 0; cs < 4; cs++) {
                        int c = 2*cs + kxp;
                        int cq = cs + kxp;
#pragma unroll
                        for (int j = 0; j < 2; j++) {
                            ffma2(acc[r][c][j], vb[r][cq],     wr[0][j]);
                            ffma2(acc[r][c][j], vb[r][cq+1],   wr[1][j]);
                            ffma2(acc[r][c][j], vb[r+1][cq],   wr[2][j]);
                            ffma2(acc[r][c][j], vb[r+1][cq+1], wr[3][j]);
                        }
                    }
                }
            }
        }
        __syncthreads();
    }
#pragma unroll
    for (int r = 0; r < 2; r++)
#pragma unroll
        for (int c = 0; c < 8; c++)
#pragma unroll
            for (int j = 0; j < 2; j++) {
                int oc = ocb + ocg*4 + 2*j;
                int oy = ry0 + row0 + r, ox = cx0 + col0 + c;
                float v0 = fmaxf(lo32(acc[r][c][j]) + bias[oc], 0.f);
                float v1 = fmaxf(hi32(acc[r][c][j]) + bias[oc+1], 0.f);
                out[(((size_t)b*Cout + oc)*64 + oy)*64 + ox] = v0;
                out[(((size_t)b*Cout + oc+1)*64 + oy)*64 + ox] = v1;
            }
}

// ---------------- dt2: convT (64->3), 4-oc ----------------
__global__ void convt4s2_kernel(const float* __restrict__ in, const float* __restrict__ w,
                                const float* __restrict__ bias, float* __restrict__ out,
                                int Cin, int Hin, int Win, int Cout, int inRelu, int outRelu)
{
    __shared__ float s_in[8][10][12];
    __shared__ float s_w[4][8][16];
    int tid = threadIdx.x;
    int Hout = Hin * 2, Wout = Win * 2;
    int ntx = Wout >> 4;
    int ox0 = (blockIdx.x % ntx) << 4, oy0 = (blockIdx.x / ntx) << 4;
    int b = blockIdx.z;
    int px = tid & 15, py = tid >> 4;
    int iy0 = oy0 >> 1, ix0 = ox0 >> 1;
    float acc[4];
#pragma unroll
    for (int i = 0; i < 4; i++) acc[i] = 0.f;

    for (int c0 = 0; c0 < Cin; c0 += 8) {
        for (int i = tid; i < 8 * 10 * 10; i += 256) {
            int ci = i / 100; int rr = (i / 10) % 10; int col = i % 10;
            int gy = iy0 - 1 + rr, gx = ix0 - 1 + col;
            float v = 0.f;
            if ((unsigned)gy < (unsigned)Hin && (unsigned)gx < (unsigned)Win)
                v = in[((b*Cin + c0 + ci)*Hin + gy)*Win + gx];
            if (inRelu) v = fmaxf(v, 0.f);
            s_in[ci][rr][col] = v;
        }
        for (int i = tid; i < 4 * 8 * 16; i += 256) {
            int oc = i >> 7; int ci = (i >> 4) & 7; int k = i & 15;
            s_w[oc][ci][k] = (oc < Cout) ? w[((size_t)oc * Cin + c0 + ci)*16 + k] : 0.f;
        }
        __syncthreads();
        int ky0 = py & 1, kx0 = px & 1;
        int r0 = (py + ky0) >> 1;
        int q0 = (px + kx0) >> 1;
#pragma unroll
        for (int ci = 0; ci < 8; ci++) {
            float v00 = s_in[ci][r0][q0];
            float v01 = s_in[ci][r0][q0 + 1];
            float v10 = s_in[ci][r0 + 1][q0];
            float v11 = s_in[ci][r0 + 1][q0 + 1];
#pragma unroll
            for (int oc = 0; oc < 4; oc++) {
                float a = acc[oc];
                a += v00 * s_w[oc][ci][ky0*4 + kx0];
                a += v01 * s_w[oc][ci][ky0*4 + kx0 + 2];
                a += v10 * s_w[oc][ci][(ky0+2)*4 + kx0];
                a += v11 * s_w[oc][ci][(ky0+2)*4 + kx0 + 2];
                acc[oc] = a;
            }
        }
        __syncthreads();
    }
#pragma unroll
    for (int oc = 0; oc < 4; oc++) {
        if (oc < Cout) {
            float r = acc[oc] + bias[oc];
            if (outRelu) r = fmaxf(r, 0.f);
            out[(((size_t)b * Cout + oc)*Hout + oy0 + py)*Wout + ox0 + px] = r;
        }
    }
}

// ---------------- finalize ----------------
__global__ void finalize_kernel(const int* __restrict__ hist, const float* __restrict__ ssep,
                                float* __restrict__ out, int lastIdx)
{
    __shared__ float red[512];
    __shared__ float red2[256];
    int t = threadIdx.x;
    float p = hist[t] * (1.0f / 32768.0f);
    red[t] = p * logf(p + 1e-10f);
    if (t < 256) red2[t] = ssep[t];
    __syncthreads();
    for (int st = 256; st > 0; st >>= 1) {
        if (t < st) red[t] += red[t + st];
        __syncthreads();
    }
    for (int st = 128; st > 0; st >>= 1) {
        if (t < st) red2[t] += red2[t + st];
        __syncthreads();
    }
    if (t == 0) {
        out[0] = red2[0] * 1.25f / (32768.0f * 64.0f);
        out[lastIdx] = expf(-red[0]);
    }
}

// ---------------- launch ----------------
extern "C" void kernel_launch(void* const* d_in, const int* in_sizes, int n_in,
                              void* d_out, int out_size)
{
    const float* x     = (const float*)d_in[0];
    const float* e_w1  = (const float*)d_in[1];
    const float* e_b1  = (const float*)d_in[2];
    const float* e_w2  = (const float*)d_in[3];
    const float* e_b2  = (const float*)d_in[4];
    const float* e_w3  = (const float*)d_in[5];
    const float* e_b3  = (const float*)d_in[6];
    const float* e_r1a = (const float*)d_in[7];
    const float* e_r1b = (const float*)d_in[8];
    const float* e_r2a = (const float*)d_in[9];
    const float* e_r2b = (const float*)d_in[10];
    const float* pre_w = (const float*)d_in[11];
    const float* pre_b = (const float*)d_in[12];
    const float* cb    = (const float*)d_in[13];
    const float* d_w1  = (const float*)d_in[14];
    const float* d_b1  = (const float*)d_in[15];
    const float* d_r1a = (const float*)d_in[16];
    const float* d_r1b = (const float*)d_in[17];
    const float* d_r2a = (const float*)d_in[18];
    const float* d_r2b = (const float*)d_in[19];
    const float* dt_w1 = (const float*)d_in[20];
    const float* dt_b1 = (const float*)d_in[21];
    const float* dt_w2 = (const float*)d_in[22];
    const float* dt_b2 = (const float*)d_in[23];
    float* out = (float*)d_out;

    float *A, *Bb, *C, *R, *Z, *Q, *ssep; int* hist;
    cudaGetSymbolAddress((void**)&A,    g_A);
    cudaGetSymbolAddress((void**)&Bb,   g_B);
    cudaGetSymbolAddress((void**)&C,    g_C);
    cudaGetSymbolAddress((void**)&R,    g_R);
    cudaGetSymbolAddress((void**)&Z,    g_Z);
    cudaGetSymbolAddress((void**)&Q,    g_Q);
    cudaGetSymbolAddress((void**)&ssep, g_ssep);
    cudaGetSymbolAddress((void**)&hist, g_hist);

    zero_kernel<<<2, 256>>>(hist);

    // ---- encoder ----
    conv_k4s2_kernel<<<dim3(16, 8, BATCH), 256>>>(x, e_w1, e_b1, A, 3, 128, 128, 64, 64, 64, 1);
    convk4s2_f2_kernel<<<dim3(4, 2, BATCH), 256>>>(A, e_w2, e_b2, Bb, 64, 128);
    // e3: full Cin=128, 4 oc-groups of 32
    conv3x3_u<<<dim3(2, 4, BATCH), 256>>>(Bb, e_w3, e_b3, C, 128, 128, 128, 0, 0);
    // res1: Cin-split 4 x 32ch -> partials; 1x1 sums
    conv3x3_u<<<dim3(2, 4, BATCH), 256>>>(C, e_r1a, nullptr, R, 128, 32, 32, 1, 1);
    conv1x1_f2_kernel<<<dim3(4, 4, BATCH), 256>>>(R, e_r1b, nullptr, C, C, 32, 128, 4);
    conv3x3_u<<<dim3(2, 4, BATCH), 256>>>(C, e_r2a, nullptr, R, 128, 32, 32, 1, 1);
    conv1x1_f2_kernel<<<dim3(4, 4, BATCH), 256>>>(R, e_r2b, nullptr, C, C, 32, 128, 4);
    conv1x1_f2_kernel<<<dim3(4, 2, BATCH), 256>>>(C, pre_w, pre_b, nullptr, Z, 128, 64, 1);

    // ---- VQ ----
    vq_kernel<<<256, 128>>>(Z, cb, Q, hist, ssep);

    // ---- decoder ----
    conv3x3_u<<<dim3(2, 4, BATCH), 256>>>(Q, d_w1, d_b1, Bb, 64, 64, 128, 0, 0);
    conv3x3_u<<<dim3(2, 4, BATCH), 256>>>(Bb, d_r1a, nullptr, R, 128, 32, 32, 1, 1);
    conv1x1_f2_kernel<<<dim3(4, 4, BATCH), 256>>>(R, d_r1b, nullptr, Bb, Bb, 32, 128, 4);
    conv3x3_u<<<dim3(2, 4, BATCH), 256>>>(Bb, d_r2a, nullptr, R, 128, 32, 32, 1, 1);
    conv1x1_f2_kernel<<<dim3(4, 4, BATCH), 256>>>(R, d_r2b, nullptr, Bb, Bb, 32, 128, 4);
    convt_f2_kernel<<<dim3(8, 2, BATCH), 256>>>(Bb, dt_w1, dt_b1, A, 128, 64);
    convt4s2_kernel<<<dim3(64, 1, BATCH), 256>>>(A, dt_w2, dt_b2, out + 1, 64, 64, 64, 3, 0, 0);

    finalize_kernel<<<1, 512>>>(hist, ssep, out, out_size - 1);
}

// round 9
// speedup vs baseline: 1.3269x; 1.1613x over previous
#include <cuda_runtime.h>
#include <cuda_bf16.h>
#include <math.h>

typedef unsigned long long ull;

// ---------------- packed f32x2 helpers (scalar kernels) ----------------
__device__ __forceinline__ ull pack2(float lo, float hi) {
    ull r; asm("mov.b64 %0, {%1, %2};" : "=l"(r) : "f"(lo), "f"(hi)); return r;
}
__device__ __forceinline__ ull bc2(float v) { return pack2(v, v); }
__device__ __forceinline__ void ffma2(ull& d, ull a, ull b) {
    asm("fma.rn.f32x2 %0, %1, %2, %0;" : "+l"(d) : "l"(a), "l"(b));
}
__device__ __forceinline__ float lo32(ull v) { return __uint_as_float((unsigned)v); }
__device__ __forceinline__ float hi32(ull v) { return __uint_as_float((unsigned)(v >> 32)); }

// ---------------- mma.sync helpers (sm_80+, valid on base sm_103) ----------------
__device__ __forceinline__ unsigned s2u(const void* p) {
    unsigned a; asm("{ .reg .u64 t; cvta.to.shared.u64 t, %1; cvt.u32.u64 %0, t; }" : "=r"(a) : "l"(p));
    return a;
}
__device__ __forceinline__ void ldsm4t(unsigned* r, unsigned addr) {
    asm volatile("ldmatrix.sync.aligned.m8n8.x4.trans.shared.b16 {%0,%1,%2,%3}, [%4];"
                 : "=r"(r[0]), "=r"(r[1]), "=r"(r[2]), "=r"(r[3]) : "r"(addr));
}
__device__ __forceinline__ void mma16816(float* c, const unsigned* a, const unsigned* b) {
    asm volatile(
        "mma.sync.aligned.m16n8k16.row.col.f32.bf16.bf16.f32 "
        "{%0,%1,%2,%3}, {%4,%5,%6,%7}, {%8,%9}, {%0,%1,%2,%3};"
        : "+f"(c[0]), "+f"(c[1]), "+f"(c[2]), "+f"(c[3])
        : "r"(a[0]), "r"(a[1]), "r"(a[2]), "r"(a[3]), "r"(b[0]), "r"(b[1]));
}

// ---------------- scratch ----------------
#define BATCH 32
__device__ float g_A[BATCH*64*64*64];
__device__ float g_B[BATCH*128*32*32];
__device__ float g_C[BATCH*128*32*32];
__device__ float g_R[BATCH*32*32*32];
__device__ float g_Z[BATCH*64*32*32];
__device__ float g_Q[BATCH*64*32*32];
__device__ int   g_hist[512];
__device__ float g_ssep[256];
// staged split-bf16: 3 kx-shifted, 34-row-padded planes. plane = kx*NP + (b*C+ci)
__device__ __align__(16) __nv_bfloat16 g_Sh[3*4096*1088];
__device__ __align__(16) __nv_bfloat16 g_Sl[3*4096*1088];
// staged weights: [tap][ci][oc]
__device__ __align__(16) __nv_bfloat16 g_Wh[9*128*128];
__device__ __align__(16) __nv_bfloat16 g_Wl[9*128*128];

__global__ void zero_kernel(int* hist) {
    int t = blockIdx.x * blockDim.x + threadIdx.x;
    if (t < 512) hist[t] = 0;
}

// ---------------- stage input ----------------
__global__ void stage_in_kernel(const float* __restrict__ in, __nv_bfloat16* __restrict__ sh,
                                __nv_bfloat16* __restrict__ sl, int NP, int doRelu)
{
    int plane = blockIdx.x;
    const float* src = in + (size_t)plane * 1024;
    for (int i = threadIdx.x; i < 3*1088; i += 256) {
        int kx = i / 1088; int r = (i % 1088) / 32; int c = i & 31;
        float v = 0.f;
        int sy = r - 1, sx = c + kx - 1;
        if ((unsigned)sy < 32u && (unsigned)sx < 32u) v = src[sy*32 + sx];
        if (doRelu) v = fmaxf(v, 0.f);
        __nv_bfloat16 h = __float2bfloat16(v);
        __nv_bfloat16 l = __float2bfloat16(v - __bfloat162float(h));
        size_t o = ((size_t)kx * NP + plane) * 1088 + r*32 + c;
        sh[o] = h; sl[o] = l;
    }
}

// ---------------- stage weights ----------------
__global__ void stage_w_kernel(const float* __restrict__ w, __nv_bfloat16* __restrict__ wh,
                               __nv_bfloat16* __restrict__ wl, int Cin, int Cout)
{
    int n = Cin * Cout * 9;
    for (int i = blockIdx.x*256 + threadIdx.x; i < n; i += gridDim.x*256) {
        int oc = i / (Cin*9); int rr = i % (Cin*9); int ci = rr / 9; int t = rr % 9;
        float v = w[i];
        __nv_bfloat16 h = __float2bfloat16(v);
        __nv_bfloat16 l = __float2bfloat16(v - __bfloat162float(h));
        size_t dst = ((size_t)t * Cin + ci) * Cout + oc;
        wh[dst] = h; wl[dst] = l;
    }
}

// ---------------- warp-MMA 3x3 conv: M=128 (4r x 32c), N=NT, K=9*Cin ----------------
// grid(8, Cout/NT, B), 256 thr = 8 warps (4 M-strips x 2 N-strips).
// Split-bf16: AhBh + AhBl + AlBh.
__global__ void __launch_bounds__(256)
conv3x3_wmma(const __nv_bfloat16* __restrict__ sh, const __nv_bfloat16* __restrict__ sl,
             const __nv_bfloat16* __restrict__ wh, const __nv_bfloat16* __restrict__ wl,
             const float* __restrict__ bias, float* __restrict__ out,
             int Cin, int Cout, int NT, int NP)
{
    // A: [32 k][136 m-pitch] bf16 (272B rows, 17x16B -> ldsm conflict-free)
    // B: [32 k][72 n-pitch]  bf16 (144B rows, 9x16B  -> conflict-free)
    __shared__ __align__(16) __nv_bfloat16 sAh[32*136], sAl[32*136];
    __shared__ __align__(16) __nv_bfloat16 sBh[32*72],  sBl[32*72];
    int tid = threadIdx.x, lane = tid & 31, warp = tid >> 5;
    int wm = warp >> 1, wn = warp & 1;
    int warpN = NT >> 1;            // 32 or 16
    int nfrags = warpN >> 3;        // 4 or 2
    unsigned aH = s2u(sAh), aL = s2u(sAl), bH = s2u(sBh), bL = s2u(sBl);

    int y0 = blockIdx.x * 4, ocb = blockIdx.y * NT, b = blockIdx.z;
    float acc[2][4][4];
#pragma unroll
    for (int mf = 0; mf < 2; mf++)
#pragma unroll
        for (int nf = 0; nf < 4; nf++)
#pragma unroll
            for (int j = 0; j < 4; j++) acc[mf][nf][j] = 0.f;

    int sub = lane >> 3, r = lane & 7;
    int nb = NT >> 3;  // uint4 per B row

    for (int tap = 0; tap < 9; tap++) {
        int ky = tap / 3, kx = tap % 3;
        for (int c0 = 0; c0 < Cin; c0 += 32) {
            size_t gbase = (size_t)kx * NP + (size_t)b * Cin + c0;
            // A tiles: 32 ci-rows x 128 m contiguous (4 padded plane rows)
            for (int i = tid; i < 512; i += 256) {
                int ci = i >> 4, q = i & 15;
                size_t go = (gbase + ci) * 1088 + (size_t)(y0 + ky) * 32;
                ((uint4*)(sAh + ci*136))[q] = ((const uint4*)(sh + go))[q];
                ((uint4*)(sAl + ci*136))[q] = ((const uint4*)(sl + go))[q];
            }
            // B tiles: 32 ci-rows x NT oc contiguous
            for (int i = tid; i < 32*nb; i += 256) {
                int ci = i / nb, q = i % nb;
                size_t wsrc = ((size_t)tap * Cin + c0 + ci) * Cout + ocb;
                ((uint4*)(sBh + ci*72))[q] = ((const uint4*)(wh + wsrc))[q];
                ((uint4*)(sBl + ci*72))[q] = ((const uint4*)(wl + wsrc))[q];
            }
            __syncthreads();
#pragma unroll
            for (int kf = 0; kf < 2; kf++) {
                unsigned Ah[2][4], Al[2][4];
                int akrow = kf*16 + ((sub & 2) ? 8 : 0) + r;
                int acoff = (sub & 1) ? 8 : 0;
#pragma unroll
                for (int mf = 0; mf < 2; mf++) {
                    unsigned off = (unsigned)(akrow*136 + wm*32 + mf*16 + acoff) * 2;
                    ldsm4t(Ah[mf], aH + off);
                    ldsm4t(Al[mf], aL + off);
                }
                unsigned Bh[4][2], Bl[4][2];
                int bkrow = kf*16 + ((sub & 1) ? 8 : 0) + r;
                int bcoff = (sub & 2) ? 8 : 0;
#pragma unroll
                for (int nf2 = 0; nf2 < 4; nf2 += 2) {
                    if (nf2 < nfrags) {
                        unsigned off = (unsigned)(bkrow*72 + wn*warpN + nf2*8 + bcoff) * 2;
                        unsigned t4[4];
                        ldsm4t(t4, bH + off);
                        Bh[nf2][0] = t4[0]; Bh[nf2][1] = t4[1];
                        Bh[nf2+1][0] = t4[2]; Bh[nf2+1][1] = t4[3];
                        ldsm4t(t4, bL + off);
                        Bl[nf2][0] = t4[0]; Bl[nf2][1] = t4[1];
                        Bl[nf2+1][0] = t4[2]; Bl[nf2+1][1] = t4[3];
                    }
                }
#pragma unroll
                for (int mf = 0; mf < 2; mf++)
#pragma unroll
                    for (int nf = 0; nf < 4; nf++) {
                        if (nf < nfrags) {
                            mma16816(acc[mf][nf], Ah[mf], Bh[nf]);
                            mma16816(acc[mf][nf], Ah[mf], Bl[nf]);
                            mma16816(acc[mf][nf], Al[mf], Bh[nf]);
                        }
                    }
            }
            __syncthreads();
        }
    }

    // epilogue: c0=(g,2tig) c1=(g,2tig+1) c2=(g+8,2tig) c3=(g+8,2tig+1)
    int g = lane >> 2, tig = lane & 3;
    float* ob = out + (size_t)b * Cout * 1024;
#pragma unroll
    for (int mf = 0; mf < 2; mf++) {
        int m1 = wm*32 + mf*16 + g;
        int m2 = m1 + 8;
        int p1 = (y0 + (m1 >> 5))*32 + (m1 & 31);
        int p2 = (y0 + (m2 >> 5))*32 + (m2 & 31);
#pragma unroll
        for (int nf = 0; nf < 4; nf++) {
            if (nf < nfrags) {
                int n0 = ocb + wn*warpN + nf*8 + 2*tig;
                float b0 = bias ? bias[n0] : 0.f;
                float b1 = bias ? bias[n0+1] : 0.f;
                ob[(size_t)n0*1024 + p1]     = acc[mf][nf][0] + b0;
                ob[(size_t)(n0+1)*1024 + p1] = acc[mf][nf][1] + b1;
                ob[(size_t)n0*1024 + p2]     = acc[mf][nf][2] + b0;
                ob[(size_t)(n0+1)*1024 + p2] = acc[mf][nf][3] + b1;
            }
        }
    }
}

// ---------------- conv1: k=4 s=2 p=1, Cin=3 (scalar) ----------------
__global__ void conv_k4s2_kernel(const float* __restrict__ in, const float* __restrict__ w,
                                 const float* __restrict__ bias, float* __restrict__ out,
                                 int Cin, int Hin, int Win, int Cout, int Hout, int Wout,
                                 int outRelu)
{
    __shared__ float s_in[8][34][36];
    __shared__ float s_w[8][8][16];
    int tid = threadIdx.x;
    int ntx = Wout >> 4;
    int tx0 = (blockIdx.x % ntx) << 4, ty0 = (blockIdx.x / ntx) << 4;
    int ocb = blockIdx.y << 3;
    int b = blockIdx.z;
    int px = tid & 15, py = tid >> 4;
    float acc[8];
#pragma unroll
    for (int i = 0; i < 8; i++) acc[i] = 0.f;

    for (int c0 = 0; c0 < Cin; c0 += 8) {
        int cc = min(8, Cin - c0);
        for (int i = tid; i < cc * 34 * 34; i += 256) {
            int ci = i / (34*34); int rr = (i / 34) % 34; int col = i % 34;
            int gy = 2*ty0 - 1 + rr, gx = 2*tx0 - 1 + col;
            float v = 0.f;
            if ((unsigned)gy < (unsigned)Hin && (unsigned)gx < (unsigned)Win)
                v = in[((b*Cin + c0 + ci)*Hin + gy)*Win + gx];
            s_in[ci][rr][col] = v;
        }
        for (int i = tid; i < 8 * cc * 16; i += 256) {
            int oc = i / (cc*16); int ci = (i / 16) % cc; int k = i & 15;
            s_w[oc][ci][k] = w[((ocb+oc)*Cin + c0 + ci)*16 + k];
        }
        __syncthreads();
        for (int ci = 0; ci < cc; ci++) {
            float v[16];
#pragma unroll
            for (int ky = 0; ky < 4; ky++)
#pragma unroll
                for (int kx = 0; kx < 4; kx++)
                    v[ky*4+kx] = s_in[ci][2*py + ky][2*px + kx];
#pragma unroll
            for (int oc = 0; oc < 8; oc++) {
                float a = acc[oc];
#pragma unroll
                for (int k = 0; k < 16; k++) a += v[k] * s_w[oc][ci][k];
                acc[oc] = a;
            }
        }
        __syncthreads();
    }
#pragma unroll
    for (int oc = 0; oc < 8; oc++) {
        float r = acc[oc] + bias[ocb + oc];
        if (outRelu) r = fmaxf(r, 0.f);
        out[((b*Cout + ocb + oc)*Hout + ty0 + py)*Wout + tx0 + px] = r;
    }
}

// ---------------- conv2: k=4 s=2 p=1 packed ----------------
__global__ void __launch_bounds__(256, 2)
convk4s2_f2_kernel(const float* __restrict__ in, const float* __restrict__ w,
                   const float* __restrict__ bias, float* __restrict__ out,
                   int Cin, int Cout)
{
    __shared__ float s_in[4][18][69];
    __shared__ ull s_w[4][16][32];
    int tid = threadIdx.x;
    int pos = tid & 31, ocg = tid >> 5;
    int posx = pos & 7, posy = pos >> 3;
    int col0 = posx * 4, row0 = posy * 2;
    int ry0 = blockIdx.x * 8;
    int ocb = blockIdx.y * 64;
    int b = blockIdx.z;
    ull acc[2][4][4];
#pragma unroll
    for (int r = 0; r < 2; r++)
#pragma unroll
        for (int c = 0; c < 4; c++)
#pragma unroll
            for (int j = 0; j < 4; j++) acc[r][c][j] = 0ull;

    float* swf = (float*)s_w;
    for (int c0 = 0; c0 < Cin; c0 += 4) {
        for (int i = tid; i < 4*18*66; i += 256) {
            int ci = i / (18*66); int rr = (i / 66) % 18; int cc = i % 66;
            int gy = 2*ry0 - 1 + rr, gx = cc - 1;
            float v = 0.f;
            if ((unsigned)gy < 64u && (unsigned)gx < 64u)
                v = in[((b*Cin + c0 + ci)*64 + gy)*64 + gx];
            s_in[ci][rr][cc] = v;
        }
        for (int i = tid; i < 64*64; i += 256) {
            int ocl = i >> 6; int t = i & 63; int ci = t >> 4; int k = t & 15;
            swf[(ci*16 + k)*64 + ocl] = w[(ocb + ocl)*Cin*16 + (c0 + ci)*16 + k];
        }
        __syncthreads();
#pragma unroll
        for (int ci = 0; ci < 4; ci++) {
#pragma unroll
            for (int ky = 0; ky < 4; ky++) {
#pragma unroll
                for (int r = 0; r < 2; r++) {
                    int rr = 2*row0 + 2*r + ky;
                    ull vb[10];
#pragma unroll
                    for (int t = 0; t < 10; t++) vb[t] = bc2(s_in[ci][rr][2*col0 + t]);
#pragma unroll
                    for (int kx = 0; kx < 4; kx++) {
                        ull wr[4];
#pragma unroll
                        for (int j = 0; j < 4; j++) wr[j] = s_w[ci][ky*4+kx][ocg*4 + j];
#pragma unroll
                        for (int c = 0; c < 4; c++)
#pragma unroll
                            for (int j = 0; j < 4; j++)
                                ffma2(acc[r][c][j], vb[2*c+kx], wr[j]);
                    }
                }
            }
        }
        __syncthreads();
    }
#pragma unroll
    for (int r = 0; r < 2; r++)
#pragma unroll
        for (int c = 0; c < 4; c++)
#pragma unroll
            for (int j = 0; j < 4; j++) {
                int oc = ocb + ocg*8 + 2*j;
                int row = ry0 + row0 + r, col = col0 + c;
                float v0 = fmaxf(lo32(acc[r][c][j]) + bias[oc], 0.f);
                float v1 = fmaxf(hi32(acc[r][c][j]) + bias[oc+1], 0.f);
                out[((b*Cout + oc)*32 + row)*32 + col] = v0;
                out[((b*Cout + oc+1)*32 + row)*32 + col] = v1;
            }
}

// ---------------- conv 1x1: relu(in) @ w, +bias, +res ----------------
__global__ void __launch_bounds__(256, 3)
conv1x1_f2_kernel(const float* __restrict__ in, const float* __restrict__ w,
                  const float* __restrict__ bias, const float* __restrict__ hres,
                  float* __restrict__ out, int Cin, int Cout)
{
    __shared__ ull s_w[128][16];
    int tid = threadIdx.x;
    int pos = tid & 63, ocg = tid >> 6;
    int s0 = blockIdx.x * 256 + pos * 4;
    int ocb = blockIdx.y * 32;
    int b = blockIdx.z;
    float* swf = (float*)s_w;
    for (int i = tid; i < Cin * 32; i += 256) {
        int ocl = i / Cin; int ci = i % Cin;
        swf[ci*32 + ocl] = w[(ocb + ocl)*Cin + ci];
    }
    __syncthreads();
    ull acc[4][4];
#pragma unroll
    for (int p = 0; p < 4; p++)
#pragma unroll
        for (int j = 0; j < 4; j++) acc[p][j] = 0ull;

    for (int ci = 0; ci < Cin; ci++) {
        float4 iv = *(const float4*)&in[((size_t)(b*Cin + ci) << 10) + s0];
        ull b0 = bc2(fmaxf(iv.x, 0.f)), b1 = bc2(fmaxf(iv.y, 0.f));
        ull b2 = bc2(fmaxf(iv.z, 0.f)), b3 = bc2(fmaxf(iv.w, 0.f));
        ull wr[4];
#pragma unroll
        for (int j = 0; j < 4; j++) wr[j] = s_w[ci][ocg*4 + j];
#pragma unroll
        for (int j = 0; j < 4; j++) {
            ffma2(acc[0][j], b0, wr[j]);
            ffma2(acc[1][j], b1, wr[j]);
            ffma2(acc[2][j], b2, wr[j]);
            ffma2(acc[3][j], b3, wr[j]);
        }
    }
#pragma unroll
    for (int j = 0; j < 4; j++) {
#pragma unroll
        for (int lane = 0; lane < 2; lane++) {
            int oc = ocb + ocg*8 + 2*j + lane;
            size_t base = (((size_t)b*Cout + oc) << 10) + s0;
            float bv = bias ? bias[oc] : 0.f;
            float4 hv = make_float4(0.f, 0.f, 0.f, 0.f);
            if (hres) hv = *(const float4*)&hres[base];
            float4 ov;
            ov.x = (lane ? hi32(acc[0][j]) : lo32(acc[0][j])) + bv + hv.x;
            ov.y = (lane ? hi32(acc[1][j]) : lo32(acc[1][j])) + bv + hv.y;
            ov.z = (lane ? hi32(acc[2][j]) : lo32(acc[2][j])) + bv + hv.z;
            ov.w = (lane ? hi32(acc[3][j]) : lo32(acc[3][j])) + bv + hv.w;
            *(float4*)&out[base] = ov;
        }
    }
}

// ---------------- vector quantizer ----------------
__global__ void vq_kernel(const float* __restrict__ z, const float* __restrict__ cb,
                          float* __restrict__ qc, int* __restrict__ hist,
                          float* __restrict__ ssep)
{
    __shared__ ull s_cb[128][32];
    __shared__ float s_cn[128];
    __shared__ int s_hist[512];
    __shared__ float s_red[128];
    int tid = threadIdx.x;
    for (int i = tid; i < 512; i += 128) s_hist[i] = 0;

    int n = blockIdx.x * 128 + tid;
    int b = n >> 10, s = n & 1023;
    ull zp[32];
    float zv[64];
#pragma unroll
    for (int d = 0; d < 64; d++) zv[d] = z[(((size_t)b * 64 + d) << 10) + s];
#pragma unroll
    for (int j = 0; j < 32; j++) zp[j] = pack2(zv[2*j], zv[2*j+1]);

    const ull* cbu = (const ull*)cb;
    float best = 3.4e38f; int bi = 0;
    for (int k0 = 0; k0 < 512; k0 += 128) {
        __syncthreads();
        for (int i = tid; i < 128*32; i += 128)
            s_cb[i >> 5][i & 31] = cbu[((size_t)k0 << 5) + i];
        __syncthreads();
        {
            float cn = 0.f;
#pragma unroll
            for (int j = 0; j < 32; j++) {
                ull p = s_cb[tid][j];
                float a = lo32(p), bb = hi32(p);
                cn += a*a + bb*bb;
            }
            s_cn[tid] = cn;
        }
        __syncthreads();
        for (int k = 0; k < 128; k++) {
            ull dp = 0ull;
#pragma unroll
            for (int j = 0; j < 32; j++) ffma2(dp, zp[j], s_cb[k][j]);
            float dot = lo32(dp) + hi32(dp);
            float dd = s_cn[k] - 2.f * dot;
            if (dd < best) { best = dd; bi = k0 + k; }
        }
    }
    float sq = 0.f;
    const float* c = cb + ((size_t)bi << 6);
#pragma unroll
    for (int d = 0; d < 64; d++) {
        float cv = c[d];
        qc[(((size_t)b * 64 + d) << 10) + s] = cv;
        float df = cv - zv[d];
        sq += df * df;
    }
    atomicAdd(&s_hist[bi], 1);
    s_red[tid] = sq;
    __syncthreads();
    for (int st = 64; st > 0; st >>= 1) {
        if (tid < st) s_red[tid] += s_red[tid + st];
        __syncthreads();
    }
    if (tid == 0) ssep[blockIdx.x] = s_red[0];
    for (int i = tid; i < 512; i += 128)
        if (s_hist[i]) atomicAdd(&hist[i], s_hist[i]);
}

// ---------------- dt1: convT k=4 s=2 p=1 packed ----------------
__global__ void __launch_bounds__(256, 2)
convt_f2_kernel(const float* __restrict__ in, const float* __restrict__ w,
                const float* __restrict__ bias, float* __restrict__ out,
                int Cin, int Cout)
{
    __shared__ float s_in[8][10][21];
    __shared__ ull s_w[8][16][16];
    int tid = threadIdx.x;
    int pos = tid & 31, ocg = tid >> 5;
    int posx = pos & 3, posy = pos >> 2;
    int col0 = posx * 8, row0 = posy * 2;
    int tx = blockIdx.x & 1, ty = blockIdx.x >> 1;
    int cx0 = tx * 32, ry0 = ty * 16;
    int ocb = blockIdx.y * 32;
    int b = blockIdx.z;
    ull acc[2][8][2];
#pragma unroll
    for (int r = 0; r < 2; r++)
#pragma unroll
        for (int c = 0; c < 8; c++)
#pragma unroll
            for (int j = 0; j < 2; j++) acc[r][c][j] = 0ull;

    float* swf = (float*)s_w;
    for (int c0 = 0; c0 < Cin; c0 += 8) {
        for (int i = tid; i < 8*10*18; i += 256) {
            int ci = i / 180; int rr = (i / 18) % 10; int cc = i % 18;
            int gy = (ry0 >> 1) - 1 + rr, gx = (cx0 >> 1) - 1 + cc;
            float v = 0.f;
            if ((unsigned)gy < 32u && (unsigned)gx < 32u)
                v = fmaxf(in[((b*Cin + c0 + ci)*32 + gy)*32 + gx], 0.f);
            s_in[ci][rr][cc] = v;
        }
        for (int i = tid; i < 32*128; i += 256) {
            int ocl = i >> 7; int t = i & 127; int ci = t >> 4; int k = t & 15;
            swf[(ci*16 + k)*32 + ocl] = w[((size_t)(ocb + ocl)*Cin + c0 + ci)*16 + k];
        }
        __syncthreads();
#pragma unroll
        for (int ci = 0; ci < 8; ci++) {
            ull vb[3][6];
#pragma unroll
            for (int rr = 0; rr < 3; rr++)
#pragma unroll
                for (int cc = 0; cc < 6; cc++)
                    vb[rr][cc] = bc2(s_in[ci][posy + rr][posx*4 + cc]);
#pragma unroll
            for (int r = 0; r < 2; r++) {
#pragma unroll
                for (int kxp = 0; kxp < 2; kxp++) {
                    ull wr[4][2];
                    int t0 = r*4 + kxp, t2 = (r+2)*4 + kxp;
#pragma unroll
                    for (int j = 0; j < 2; j++) {
                        wr[0][j] = s_w[ci][t0][ocg*2 + j];
                        wr[1][j] = s_w[ci][t0+2][ocg*2 + j];
                        wr[2][j] = s_w[ci][t2][ocg*2 + j];
                        wr[3][j] = s_w[ci][t2+2][ocg*2 + j];
                    }
#pragma unroll
                    for (int cs = 0; cs < 4; cs++) {
                        int c = 2*cs + kxp;
                        int cq = cs + kxp;
#pragma unroll
                        for (int j = 0; j < 2; j++) {
                            ffma2(acc[r][c][j], vb[r][cq],     wr[0][j]);
                            ffma2(acc[r][c][j], vb[r][cq+1],   wr[1][j]);
                            ffma2(acc[r][c][j], vb[r+1][cq],   wr[2][j]);
                            ffma2(acc[r][c][j], vb[r+1][cq+1], wr[3][j]);
                        }
                    }
                }
            }
        }
        __syncthreads();
    }
#pragma unroll
    for (int r = 0; r < 2; r++)
#pragma unroll
        for (int c = 0; c < 8; c++)
#pragma unroll
            for (int j = 0; j < 2; j++) {
                int oc = ocb + ocg*4 + 2*j;
                int oy = ry0 + row0 + r, ox = cx0 + col0 + c;
                float v0 = fmaxf(lo32(acc[r][c][j]) + bias[oc], 0.f);
                float v1 = fmaxf(hi32(acc[r][c][j]) + bias[oc+1], 0.f);
                out[(((size_t)b*Cout + oc)*64 + oy)*64 + ox] = v0;
                out[(((size_t)b*Cout + oc+1)*64 + oy)*64 + ox] = v1;
            }
}

// ---------------- dt2: convT (64->3), 4-oc ----------------
__global__ void convt4s2_kernel(const float* __restrict__ in, const float* __restrict__ w,
                                const float* __restrict__ bias, float* __restrict__ out,
                                int Cin, int Hin, int Win, int Cout, int inRelu, int outRelu)
{
    __shared__ float s_in[8][10][12];
    __shared__ float s_w[4][8][16];
    int tid = threadIdx.x;
    int Hout = Hin * 2, Wout = Win * 2;
    int ntx = Wout >> 4;
    int ox0 = (blockIdx.x % ntx) << 4, oy0 = (blockIdx.x / ntx) << 4;
    int b = blockIdx.z;
    int px = tid & 15, py = tid >> 4;
    int iy0 = oy0 >> 1, ix0 = ox0 >> 1;
    float acc[4];
#pragma unroll
    for (int i = 0; i < 4; i++) acc[i] = 0.f;

    for (int c0 = 0; c0 < Cin; c0 += 8) {
        for (int i = tid; i < 8 * 10 * 10; i += 256) {
            int ci = i / 100; int rr = (i / 10) % 10; int col = i % 10;
            int gy = iy0 - 1 + rr, gx = ix0 - 1 + col;
            float v = 0.f;
            if ((unsigned)gy < (unsigned)Hin && (unsigned)gx < (unsigned)Win)
                v = in[((b*Cin + c0 + ci)*Hin + gy)*Win + gx];
            if (inRelu) v = fmaxf(v, 0.f);
            s_in[ci][rr][col] = v;
        }
        for (int i = tid; i < 4 * 8 * 16; i += 256) {
            int oc = i >> 7; int ci = (i >> 4) & 7; int k = i & 15;
            s_w[oc][ci][k] = (oc < Cout) ? w[((size_t)oc * Cin + c0 + ci)*16 + k] : 0.f;
        }
        __syncthreads();
        int ky0 = py & 1, kx0 = px & 1;
        int r0 = (py + ky0) >> 1;
        int q0 = (px + kx0) >> 1;
#pragma unroll
        for (int ci = 0; ci < 8; ci++) {
            float v00 = s_in[ci][r0][q0];
            float v01 = s_in[ci][r0][q0 + 1];
            float v10 = s_in[ci][r0 + 1][q0];
            float v11 = s_in[ci][r0 + 1][q0 + 1];
#pragma unroll
            for (int oc = 0; oc < 4; oc++) {
                float a = acc[oc];
                a += v00 * s_w[oc][ci][ky0*4 + kx0];
                a += v01 * s_w[oc][ci][ky0*4 + kx0 + 2];
                a += v10 * s_w[oc][ci][(ky0+2)*4 + kx0];
                a += v11 * s_w[oc][ci][(ky0+2)*4 + kx0 + 2];
                acc[oc] = a;
            }
        }
        __syncthreads();
    }
#pragma unroll
    for (int oc = 0; oc < 4; oc++) {
        if (oc < Cout) {
            float r = acc[oc] + bias[oc];
            if (outRelu) r = fmaxf(r, 0.f);
            out[(((size_t)b * Cout + oc)*Hout + oy0 + py)*Wout + ox0 + px] = r;
        }
    }
}

// ---------------- finalize ----------------
__global__ void finalize_kernel(const int* __restrict__ hist, const float* __restrict__ ssep,
                                float* __restrict__ out, int lastIdx)
{
    __shared__ float red[512];
    __shared__ float red2[256];
    int t = threadIdx.x;
    float p = hist[t] * (1.0f / 32768.0f);
    red[t] = p * logf(p + 1e-10f);
    if (t < 256) red2[t] = ssep[t];
    __syncthreads();
    for (int st = 256; st > 0; st >>= 1) {
        if (t < st) red[t] += red[t + st];
        __syncthreads();
    }
    for (int st = 128; st > 0; st >>= 1) {
        if (t < st) red2[t] += red2[t + st];
        __syncthreads();
    }
    if (t == 0) {
        out[0] = red2[0] * 1.25f / (32768.0f * 64.0f);
        out[lastIdx] = expf(-red[0]);
    }
}

// ---------------- launch ----------------
extern "C" void kernel_launch(void* const* d_in, const int* in_sizes, int n_in,
                              void* d_out, int out_size)
{
    const float* x     = (const float*)d_in[0];
    const float* e_w1  = (const float*)d_in[1];
    const float* e_b1  = (const float*)d_in[2];
    const float* e_w2  = (const float*)d_in[3];
    const float* e_b2  = (const float*)d_in[4];
    const float* e_w3  = (const float*)d_in[5];
    const float* e_b3  = (const float*)d_in[6];
    const float* e_r1a = (const float*)d_in[7];
    const float* e_r1b = (const float*)d_in[8];
    const float* e_r2a = (const float*)d_in[9];
    const float* e_r2b = (const float*)d_in[10];
    const float* pre_w = (const float*)d_in[11];
    const float* pre_b = (const float*)d_in[12];
    const float* cb    = (const float*)d_in[13];
    const float* d_w1  = (const float*)d_in[14];
    const float* d_b1  = (const float*)d_in[15];
    const float* d_r1a = (const float*)d_in[16];
    const float* d_r1b = (const float*)d_in[17];
    const float* d_r2a = (const float*)d_in[18];
    const float* d_r2b = (const float*)d_in[19];
    const float* dt_w1 = (const float*)d_in[20];
    const float* dt_b1 = (const float*)d_in[21];
    const float* dt_w2 = (const float*)d_in[22];
    const float* dt_b2 = (const float*)d_in[23];
    float* out = (float*)d_out;

    float *A, *Bb, *C, *R, *Z, *Q, *ssep; int* hist;
    __nv_bfloat16 *Sh, *Sl, *Wh, *Wl;
    cudaGetSymbolAddress((void**)&A,    g_A);
    cudaGetSymbolAddress((void**)&Bb,   g_B);
    cudaGetSymbolAddress((void**)&C,    g_C);
    cudaGetSymbolAddress((void**)&R,    g_R);
    cudaGetSymbolAddress((void**)&Z,    g_Z);
    cudaGetSymbolAddress((void**)&Q,    g_Q);
    cudaGetSymbolAddress((void**)&ssep, g_ssep);
    cudaGetSymbolAddress((void**)&hist, g_hist);
    cudaGetSymbolAddress((void**)&Sh,   g_Sh);
    cudaGetSymbolAddress((void**)&Sl,   g_Sl);
    cudaGetSymbolAddress((void**)&Wh,   g_Wh);
    cudaGetSymbolAddress((void**)&Wl,   g_Wl);

    zero_kernel<<<2, 256>>>(hist);

    // ---- encoder ----
    conv_k4s2_kernel<<<dim3(16, 8, BATCH), 256>>>(x, e_w1, e_b1, A, 3, 128, 128, 64, 64, 64, 1);
    convk4s2_f2_kernel<<<dim3(4, 2, BATCH), 256>>>(A, e_w2, e_b2, Bb, 64, 128);

    // e3: 128->128 via tensor-core mma.sync
    stage_w_kernel<<<64, 256>>>(e_w3, Wh, Wl, 128, 128);
    stage_in_kernel<<<4096, 256>>>(Bb, Sh, Sl, 4096, 0);
    conv3x3_wmma<<<dim3(8, 2, BATCH), 256>>>(Sh, Sl, Wh, Wl, e_b3, C, 128, 128, 64, 4096);
    // res1
    stage_w_kernel<<<64, 256>>>(e_r1a, Wh, Wl, 128, 32);
    stage_in_kernel<<<4096, 256>>>(C, Sh, Sl, 4096, 1);
    conv3x3_wmma<<<dim3(8, 1, BATCH), 256>>>(Sh, Sl, Wh, Wl, nullptr, R, 128, 32, 32, 4096);
    conv1x1_f2_kernel<<<dim3(4, 4, BATCH), 256>>>(R, e_r1b, nullptr, C, C, 32, 128);
    // res2
    stage_w_kernel<<<64, 256>>>(e_r2a, Wh, Wl, 128, 32);
    stage_in_kernel<<<4096, 256>>>(C, Sh, Sl, 4096, 1);
    conv3x3_wmma<<<dim3(8, 1, BATCH), 256>>>(Sh, Sl, Wh, Wl, nullptr, R, 128, 32, 32, 4096);
    conv1x1_f2_kernel<<<dim3(4, 4, BATCH), 256>>>(R, e_r2b, nullptr, C, C, 32, 128);
    // pre-VQ 1x1 (applies res-stack final relu on input)
    conv1x1_f2_kernel<<<dim3(4, 2, BATCH), 256>>>(C, pre_w, pre_b, nullptr, Z, 128, 64);

    // ---- VQ ----
    vq_kernel<<<256, 128>>>(Z, cb, Q, hist, ssep);

    // ---- decoder ----
    stage_w_kernel<<<64, 256>>>(d_w1, Wh, Wl, 64, 128);
    stage_in_kernel<<<2048, 256>>>(Q, Sh, Sl, 2048, 0);
    conv3x3_wmma<<<dim3(8, 2, BATCH), 256>>>(Sh, Sl, Wh, Wl, d_b1, Bb, 64, 128, 64, 2048);
    stage_w_kernel<<<64, 256>>>(d_r1a, Wh, Wl, 128, 32);
    stage_in_kernel<<<4096, 256>>>(Bb, Sh, Sl, 4096, 1);
    conv3x3_wmma<<<dim3(8, 1, BATCH), 256>>>(Sh, Sl, Wh, Wl, nullptr, R, 128, 32, 32, 4096);
    conv1x1_f2_kernel<<<dim3(4, 4, BATCH), 256>>>(R, d_r1b, nullptr, Bb, Bb, 32, 128);
    stage_w_kernel<<<64, 256>>>(d_r2a, Wh, Wl, 128, 32);
    stage_in_kernel<<<4096, 256>>>(Bb, Sh, Sl, 4096, 1);
    conv3x3_wmma<<<dim3(8, 1, BATCH), 256>>>(Sh, Sl, Wh, Wl, nullptr, R, 128, 32, 32, 4096);
    conv1x1_f2_kernel<<<dim3(4, 4, BATCH), 256>>>(R, d_r2b, nullptr, Bb, Bb, 32, 128);
    convt_f2_kernel<<<dim3(8, 2, BATCH), 256>>>(Bb, dt_w1, dt_b1, A, 128, 64);
    convt4s2_kernel<<<dim3(64, 1, BATCH), 256>>>(A, dt_w2, dt_b2, out + 1, 64, 64, 64, 3, 0, 0);

    finalize_kernel<<<1, 512>>>(hist, ssep, out, out_size - 1);
}